// round 10
// baseline (speedup 1.0000x reference)
#include <cuda_runtime.h>
#include <cuda_fp16.h>
#include <math_constants.h>
#include <math.h>
#include <stdint.h>

#define Bc 16
#define Tc 1024
#define Sc 2048
#define Cc 256
#define Ec 256
#define NSEL 103     // ceil(2048/20)
#define MS 20
#define STRIDEc 20

// ---------------- scratch (device globals; no allocation allowed) ----------
__device__ float g_h[Bc*Tc*Ec];                 // out1 (fp32)
__device__ __half g_hf[Bc*Tc*Ec];               // h (fp16)
__device__ __half g_ekf[Bc*Ec*Sc];              // enc_keys fp16
__device__ __half g_evf[Bc*Sc*Ec];              // enc_values fp16
__device__ __half g_af[(size_t)Bc*Tc*Sc];       // attn fp16
__device__ float g_xmean[Bc*Sc];
__device__ float g_invn[Bc*NSEL];
__device__ float g_aa[Bc*NSEL];
__device__ float g_L[Bc*NSEL*NSEL];
__device__ int   g_mu[Bc*MS];
__device__ float g_kl;

// ---------------- small init / final ---------------------------------------
__global__ void init_k() { g_kl = 0.0f; }
__global__ void final_k(float* klout) { klout[0] = -g_kl; }

// ---------------- tf32 split (bitmask) for the weight GEMMs -----------------
__device__ __forceinline__ void split_tf32(float x, uint32_t& hi, uint32_t& lo)
{
    uint32_t xb = __float_as_uint(x);
    uint32_t h  = xb & 0xFFFFE000u;
    hi = h;
    lo = __float_as_uint(x - __uint_as_float(h));
}

#define MMA_TF32(c, a, b) \
    asm volatile("mma.sync.aligned.m16n8k8.row.col.f32.tf32.tf32.f32 " \
        "{%0,%1,%2,%3}, {%4,%5,%6,%7}, {%8,%9}, {%0,%1,%2,%3};" \
        : "+f"((c)[0]), "+f"((c)[1]), "+f"((c)[2]), "+f"((c)[3]) \
        : "r"((a)[0]), "r"((a)[1]), "r"((a)[2]), "r"((a)[3]), \
          "r"((b)[0]), "r"((b)[1]))

#define MMA_FP16(c, a, b) \
    asm volatile("mma.sync.aligned.m16n8k16.row.col.f32.f16.f16.f32 " \
        "{%0,%1,%2,%3}, {%4,%5,%6,%7}, {%8,%9}, {%0,%1,%2,%3};" \
        : "+f"((c)[0]), "+f"((c)[1]), "+f"((c)[2]), "+f"((c)[3]) \
        : "r"((a)[0]), "r"((a)[1]), "r"((a)[2]), "r"((a)[3]), \
          "r"((b)[0]), "r"((b)[1]))

#define LDSM4(r, addr) \
    asm volatile("ldmatrix.sync.aligned.m8n8.x4.shared.b16 {%0,%1,%2,%3}, [%4];" \
        : "=r"((r)[0]), "=r"((r)[1]), "=r"((r)[2]), "=r"((r)[3]) : "r"(addr))

#define LDSM4T(r, addr) \
    asm volatile("ldmatrix.sync.aligned.m8n8.x4.trans.shared.b16 {%0,%1,%2,%3}, [%4];" \
        : "=r"((r)[0]), "=r"((r)[1]), "=r"((r)[2]), "=r"((r)[3]) : "r"(addr))

__device__ __forceinline__ void cpa16(void* smem_dst, const void* gsrc)
{
    uint32_t d = (uint32_t)__cvta_generic_to_shared(smem_dst);
    asm volatile("cp.async.cg.shared.global [%0], [%1], 16;" :: "r"(d), "l"(gsrc));
}
__device__ __forceinline__ void cpa16s(uint32_t d, const void* gsrc)
{
    asm volatile("cp.async.cg.shared.global [%0], [%1], 16;" :: "r"(d), "l"(gsrc));
}
__device__ __forceinline__ void cpa_commit() { asm volatile("cp.async.commit_group;"); }
__device__ __forceinline__ void cpa_wait0()  { asm volatile("cp.async.wait_group 0;"); }
__device__ __forceinline__ void cpa_wait1()  { asm volatile("cp.async.wait_group 1;"); }

// ============================================================================
// Batched NN GEMM, single fp16, fp32 accumulate:  C = alpha * A[M,K] @ B[K,N]
// BM=128 BN=64 BK=32, 256 threads (8 warps: 4 in M x 2 in N), warp 32x32.
// 3-stage cp.async pipeline, one __syncthreads per k-iter. 3 CTAs/SM.
// ============================================================================
#define NNF_A 0
#define NNF_B 10240
#define NNF_BUF 14848
#define NNF_STAGES 3
#define NNF_SMEM (NNF_STAGES*NNF_BUF)

__global__ __launch_bounds__(256, 3)
void gemm_nn_fp16(const __half* __restrict__ A, const __half* __restrict__ B,
                  float* __restrict__ C, int M, int N, int K,
                  long long sA, long long sB, long long sC, float alpha)
{
    extern __shared__ char smdyn[];
    const int bz = blockIdx.z;
    A += (size_t)bz * sA; B += (size_t)bz * sB; C += (size_t)bz * sC;
    const int m0 = blockIdx.y * 128, n0 = blockIdx.x * 64;
    const int tid = threadIdx.x, lane = tid & 31, wid = tid >> 5;
    const int wm = (wid & 3) * 32, wn = (wid >> 2) * 32;
    const int g = lane >> 2, t = lane & 3;
    const uint32_t sbase = (uint32_t)__cvta_generic_to_shared(smdyn);

    float c[2][4][4] = {};
    const int S = K / 32;

    auto issue = [&](int kt) {
        const uint32_t base = sbase + (kt % NNF_STAGES) * NNF_BUF;
        const int k0 = kt * 32;
        #pragma unroll
        for (int j = 0; j < 2; j++) {
            int ch = tid + j * 256, row = ch >> 2, cc = ch & 3;
            cpa16s(base + NNF_A + row * 80 + cc * 16, A + (size_t)(m0 + row) * K + k0 + cc * 8);
        }
        {
            int row = tid >> 3, cc = tid & 7;
            cpa16s(base + NNF_B + row * 144 + cc * 16, B + (size_t)(k0 + row) * N + n0 + cc * 8);
        }
        cpa_commit();
    };

    issue(0);
    issue(1);
    for (int s = 0; s < S; s++) {
        if (s + 1 < S) cpa_wait1(); else cpa_wait0();
        __syncthreads();
        if (s + 2 < S) issue(s + 2);
        const uint32_t base = sbase + (s % NNF_STAGES) * NNF_BUF;
        #pragma unroll
        for (int ks = 0; ks < 2; ks++) {
            uint32_t a[2][4];
            #pragma unroll
            for (int mt = 0; mt < 2; mt++) {
                uint32_t addr = base + NNF_A
                    + (uint32_t)(wm + mt * 16 + (lane & 15)) * 80
                    + (uint32_t)(ks * 32 + (lane >> 4) * 16);
                LDSM4(a[mt], addr);
            }
            uint32_t b[2][4];
            #pragma unroll
            for (int bt = 0; bt < 2; bt++) {
                uint32_t addr = base + NNF_B
                    + (uint32_t)(ks * 16 + (lane & 15)) * 144
                    + (uint32_t)((wn + bt * 16) * 2 + (lane >> 4) * 16);
                LDSM4T(b[bt], addr);
            }
            #pragma unroll
            for (int mt = 0; mt < 2; mt++)
                #pragma unroll
                for (int nt = 0; nt < 4; nt++)
                    MMA_FP16(c[mt][nt], a[mt], (&b[nt >> 1][(nt & 1) * 2]));
        }
    }

    #pragma unroll
    for (int mt = 0; mt < 2; mt++)
        #pragma unroll
        for (int nt = 0; nt < 4; nt++) {
            int row = m0 + wm + mt * 16 + g;
            int col = n0 + wn + nt * 8 + 2 * t;
            float2 v0 = make_float2(alpha * c[mt][nt][0], alpha * c[mt][nt][1]);
            float2 v1 = make_float2(alpha * c[mt][nt][2], alpha * c[mt][nt][3]);
            *(float2*)&C[(size_t)row * N + col]       = v0;
            *(float2*)&C[(size_t)(row + 8) * N + col] = v1;
        }
}

// ============================================================================
// convert: fp32 -> fp16 (vectorized)
// ============================================================================
__global__ void convert_f16(const float4* __restrict__ src, __half2* __restrict__ h2)
{
    const int i = blockIdx.x * 256 + threadIdx.x;
    float4 v = src[i];
    h2[2*i]     = __floats2half2_rn(v.x, v.y);
    h2[2*i + 1] = __floats2half2_rn(v.z, v.w);
}

// ============================================================================
// NT GEMM (tf32 split) producing fp16 h: h = (A @ W^T + bias + add)*scale
// ============================================================================
__global__ __launch_bounds__(256, 2)
void gemm_nt_h(const float* __restrict__ A, const float* __restrict__ W,
               const float* __restrict__ bias, const float* __restrict__ add,
               __half* __restrict__ outf, int M, int N, int K, float scale)
{
    const int m0 = blockIdx.y * 128, n0 = blockIdx.x * 64;
    const int tid = threadIdx.x, lane = tid & 31, wid = tid >> 5;
    const int wm = (wid & 3) * 32, wn = (wid >> 2) * 32;
    const int g = lane >> 2, t = lane & 3;

    __shared__ float As[2][128][20];
    __shared__ float Ws[2][64][20];

    float c[2][4][4] = {};
    const int S = K / 16;

    auto issue = [&](int s, int buf) {
        const int k0 = s * 16;
        #pragma unroll
        for (int j = 0; j < 2; j++) {
            int ch = tid + j * 256;
            int row = ch >> 2, kc = ch & 3;
            cpa16(&As[buf][row][kc * 4], A + (size_t)(m0 + row) * K + k0 + kc * 4);
        }
        int wrow = tid >> 2, wkc = tid & 3;
        cpa16(&Ws[buf][wrow][wkc * 4], W + (size_t)(n0 + wrow) * K + k0 + wkc * 4);
        cpa_commit();
    };

    issue(0, 0);
    for (int s = 0; s < S; s++) {
        if (s + 1 < S) { issue(s + 1, (s + 1) & 1); cpa_wait1(); }
        else cpa_wait0();
        __syncthreads();
        const int buf = s & 1;
        #pragma unroll
        for (int kf = 0; kf < 2; kf++) {
            uint32_t ah[2][4], al[2][4];
            #pragma unroll
            for (int mt = 0; mt < 2; mt++) {
                int mr = wm + mt * 16 + g;
                split_tf32(As[buf][mr    ][kf*8 + t],     ah[mt][0], al[mt][0]);
                split_tf32(As[buf][mr + 8][kf*8 + t],     ah[mt][1], al[mt][1]);
                split_tf32(As[buf][mr    ][kf*8 + t + 4], ah[mt][2], al[mt][2]);
                split_tf32(As[buf][mr + 8][kf*8 + t + 4], ah[mt][3], al[mt][3]);
            }
            uint32_t bh[4][2], bl[4][2];
            #pragma unroll
            for (int nt = 0; nt < 4; nt++) {
                int nr = wn + nt * 8 + g;
                split_tf32(Ws[buf][nr][kf*8 + t],     bh[nt][0], bl[nt][0]);
                split_tf32(Ws[buf][nr][kf*8 + t + 4], bh[nt][1], bl[nt][1]);
            }
            #pragma unroll
            for (int mt = 0; mt < 2; mt++)
                #pragma unroll
                for (int nt = 0; nt < 4; nt++)
                    MMA_TF32(c[mt][nt], ah[mt], bh[nt]);
            #pragma unroll
            for (int mt = 0; mt < 2; mt++)
                #pragma unroll
                for (int nt = 0; nt < 4; nt++)
                    MMA_TF32(c[mt][nt], ah[mt], bl[nt]);
            #pragma unroll
            for (int mt = 0; mt < 2; mt++)
                #pragma unroll
                for (int nt = 0; nt < 4; nt++)
                    MMA_TF32(c[mt][nt], al[mt], bh[nt]);
        }
        __syncthreads();
    }

    #pragma unroll
    for (int mt = 0; mt < 2; mt++)
        #pragma unroll
        for (int nt = 0; nt < 4; nt++) {
            int row = m0 + wm + mt * 16 + g;
            int col = n0 + wn + nt * 8 + 2 * t;
            float2 bv = *(const float2*)&bias[col];
            size_t i0 = (size_t)row * N + col;
            size_t i1 = (size_t)(row + 8) * N + col;
            float2 d0 = *(const float2*)&add[i0];
            float2 d1 = *(const float2*)&add[i1];
            float v00 = (c[mt][nt][0] + bv.x + d0.x) * scale;
            float v01 = (c[mt][nt][1] + bv.y + d0.y) * scale;
            float v10 = (c[mt][nt][2] + bv.x + d1.x) * scale;
            float v11 = (c[mt][nt][3] + bv.y + d1.y) * scale;
            *(__half2*)&outf[i0] = __floats2half2_rn(v00, v01);
            *(__half2*)&outf[i1] = __floats2half2_rn(v10, v11);
        }
}

// ============================================================================
// NT GEMM with fp32 epilogue (final output): out = (A @ W^T + bias + add)*scale
// ============================================================================
__global__ __launch_bounds__(256, 2)
void gemm_nt_tc(const float* __restrict__ A, const float* __restrict__ W,
                const float* __restrict__ bias, const float* __restrict__ add,
                float* __restrict__ out, int M, int N, int K, float scale)
{
    const int m0 = blockIdx.y * 128, n0 = blockIdx.x * 64;
    const int tid = threadIdx.x, lane = tid & 31, wid = tid >> 5;
    const int wm = (wid & 3) * 32, wn = (wid >> 2) * 32;
    const int g = lane >> 2, t = lane & 3;

    __shared__ float As[2][128][20];
    __shared__ float Ws[2][64][20];

    float c[2][4][4] = {};
    const int S = K / 16;

    auto issue = [&](int s, int buf) {
        const int k0 = s * 16;
        #pragma unroll
        for (int j = 0; j < 2; j++) {
            int ch = tid + j * 256;
            int row = ch >> 2, kc = ch & 3;
            cpa16(&As[buf][row][kc * 4], A + (size_t)(m0 + row) * K + k0 + kc * 4);
        }
        int wrow = tid >> 2, wkc = tid & 3;
        cpa16(&Ws[buf][wrow][wkc * 4], W + (size_t)(n0 + wrow) * K + k0 + wkc * 4);
        cpa_commit();
    };

    issue(0, 0);
    for (int s = 0; s < S; s++) {
        if (s + 1 < S) { issue(s + 1, (s + 1) & 1); cpa_wait1(); }
        else cpa_wait0();
        __syncthreads();
        const int buf = s & 1;
        #pragma unroll
        for (int kf = 0; kf < 2; kf++) {
            uint32_t ah[2][4], al[2][4];
            #pragma unroll
            for (int mt = 0; mt < 2; mt++) {
                int mr = wm + mt * 16 + g;
                split_tf32(As[buf][mr    ][kf*8 + t],     ah[mt][0], al[mt][0]);
                split_tf32(As[buf][mr + 8][kf*8 + t],     ah[mt][1], al[mt][1]);
                split_tf32(As[buf][mr    ][kf*8 + t + 4], ah[mt][2], al[mt][2]);
                split_tf32(As[buf][mr + 8][kf*8 + t + 4], ah[mt][3], al[mt][3]);
            }
            uint32_t bh[4][2], bl[4][2];
            #pragma unroll
            for (int nt = 0; nt < 4; nt++) {
                int nr = wn + nt * 8 + g;
                split_tf32(Ws[buf][nr][kf*8 + t],     bh[nt][0], bl[nt][0]);
                split_tf32(Ws[buf][nr][kf*8 + t + 4], bh[nt][1], bl[nt][1]);
            }
            #pragma unroll
            for (int mt = 0; mt < 2; mt++)
                #pragma unroll
                for (int nt = 0; nt < 4; nt++)
                    MMA_TF32(c[mt][nt], ah[mt], bh[nt]);
            #pragma unroll
            for (int mt = 0; mt < 2; mt++)
                #pragma unroll
                for (int nt = 0; nt < 4; nt++)
                    MMA_TF32(c[mt][nt], ah[mt], bl[nt]);
            #pragma unroll
            for (int mt = 0; mt < 2; mt++)
                #pragma unroll
                for (int nt = 0; nt < 4; nt++)
                    MMA_TF32(c[mt][nt], al[mt], bh[nt]);
        }
        __syncthreads();
    }

    #pragma unroll
    for (int mt = 0; mt < 2; mt++)
        #pragma unroll
        for (int nt = 0; nt < 4; nt++) {
            int row = m0 + wm + mt * 16 + g;
            int col = n0 + wn + nt * 8 + 2 * t;
            float2 bv = *(const float2*)&bias[col];
            size_t i0 = (size_t)row * N + col;
            size_t i1 = (size_t)(row + 8) * N + col;
            float2 d0 = *(const float2*)&add[i0];
            float2 d1 = *(const float2*)&add[i1];
            float2 v0 = make_float2((c[mt][nt][0] + bv.x + d0.x) * scale,
                                    (c[mt][nt][1] + bv.y + d0.y) * scale);
            float2 v1 = make_float2((c[mt][nt][2] + bv.x + d1.x) * scale,
                                    (c[mt][nt][3] + bv.y + d1.y) * scale);
            *(float2*)&out[i0] = v0;
            *(float2*)&out[i1] = v1;
        }
}

// ---------------- row softmax (in place) + fp16 copy ------------------------
__global__ void softmax_f16(float* __restrict__ attn, __half* __restrict__ af)
{
    const size_t row = blockIdx.x;
    float* p = attn + row * (size_t)Sc;
    __half* pf = af + row * (size_t)Sc;
    const int tid = threadIdx.x;   // 256 threads, 8 elems each
    __shared__ float red[256];
    float v[8];
    float mx = -CUDART_INF_F;
    #pragma unroll
    for (int i = 0; i < 8; i++) { v[i] = p[tid + i*256]; mx = fmaxf(mx, v[i]); }
    red[tid] = mx; __syncthreads();
    for (int s = 128; s > 0; s >>= 1) { if (tid < s) red[tid] = fmaxf(red[tid], red[tid+s]); __syncthreads(); }
    mx = red[0]; __syncthreads();
    float sum = 0.0f;
    #pragma unroll
    for (int i = 0; i < 8; i++) { v[i] = __expf(v[i] - mx); sum += v[i]; }
    red[tid] = sum; __syncthreads();
    for (int s = 128; s > 0; s >>= 1) { if (tid < s) red[tid] += red[tid+s]; __syncthreads(); }
    const float inv = 1.0f / red[0];
    #pragma unroll
    for (int i = 0; i < 8; i++) {
        float a = v[i] * inv;
        p[tid + i*256] = a;
        pf[tid + i*256] = __float2half_rn(a);
    }
}

// ---------------- x_mean[b][s] = mean_t attn[b][t][s] -----------------------
__global__ void xmean_k(const float* __restrict__ attn)
{
    const int b = blockIdx.y;
    const int s = blockIdx.x * 256 + threadIdx.x;
    const float* p = attn + (size_t)b * Tc * Sc + s;
    float sum = 0.0f;
    for (int t = 0; t < Tc; t++) sum += p[(size_t)t * Sc];
    g_xmean[b * Sc + s] = sum * (1.0f / Tc);
}

// ---------------- row inv-norms of strided enc_values + aa -----------------
__global__ void norm_aa_k(const float* __restrict__ V)
{
    const int b = blockIdx.x;
    const int w = threadIdx.x >> 5, lane = threadIdx.x & 31;
    for (int n = w; n < NSEL; n += 8) {
        const float* row = V + ((size_t)b * Sc + (size_t)n * STRIDEc) * Ec;
        float s = 0.0f;
        for (int e = lane; e < Ec; e += 32) { float x = row[e]; s = fmaf(x, x, s); }
        #pragma unroll
        for (int o = 16; o; o >>= 1) s += __shfl_down_sync(0xffffffffu, s, o);
        if (lane == 0) {
            g_invn[b * NSEL + n] = rsqrtf(s);
            g_aa[b * NSEL + n]   = g_xmean[b * Sc + n * STRIDEc];
        }
    }
}

// ---------------- L[b][n][m] = aa_n aa_m * <v_n,v_m>/(|v_n||v_m|) ----------
__global__ void L_k(const float* __restrict__ V)
{
    const int b = blockIdx.x, n = blockIdx.y;
    __shared__ float vn[Ec];
    const float* rn = V + ((size_t)b * Sc + (size_t)n * STRIDEc) * Ec;
    for (int e = threadIdx.x; e < Ec; e += 128) vn[e] = rn[e];
    __syncthreads();
    const int m = threadIdx.x;
    if (m < NSEL) {
        const float* rm = V + ((size_t)b * Sc + (size_t)m * STRIDEc) * Ec;
        float d = 0.0f;
        for (int e = 0; e < Ec; e++) d = fmaf(vn[e], rm[e], d);
        float val = d * g_invn[b*NSEL + n] * g_invn[b*NSEL + m]
                      * g_aa[b*NSEL + n]   * g_aa[b*NSEL + m];
        g_L[((size_t)b * NSEL + n) * NSEL + m] = val;
    }
}

// numpy-style argmax of logf(D[n]*mask[n]): first NaN wins; strict > keeps first max
__device__ __forceinline__ int argmax_logDm(const float* D, const float* msk)
{
    int J = 0; float best = -CUDART_INF_F; bool done = false;
    for (int n = 0; n < NSEL && !done; n++) {
        float v = logf(D[n] * msk[n]);
        if (isnan(v)) { J = n; done = true; }
        else if (v > best) { best = v; J = n; }
    }
    return J;
}

// ---------------- greedy bfgm selection (sequential, tiny) -----------------
__global__ void bfgm_k()
{
    const int b = blockIdx.x, tid = threadIdx.x;  // 128 threads
    __shared__ float Cm[NSEL][MS];
    __shared__ float D[NSEL], msk[NSEL], cjs[MS];
    __shared__ float djs;
    __shared__ int Jsh, sel[MS];
    const float* L = g_L + (size_t)b * NSEL * NSEL;

    if (tid < NSEL) {
        D[tid] = L[(size_t)tid * NSEL + tid];
        msk[tid] = 1.0f;
        #pragma unroll
        for (int k = 0; k < MS; k++) Cm[tid][k] = 0.0f;
    }
    __syncthreads();
    if (tid == 0) {
        int J = argmax_logDm(D, msk);
        Jsh = J; msk[J] = 0.0f; sel[0] = J;
    }
    __syncthreads();

    for (int t = 1; t < MS; t++) {
        const int J = Jsh;
        if (tid < MS) cjs[tid] = Cm[J][tid];
        if (tid == 0) djs = D[J];
        __syncthreads();
        if (tid < NSEL) {
            float Lj = L[(size_t)J * NSEL + tid];
            float cd = 0.0f;
            #pragma unroll
            for (int k = 0; k < MS; k++) cd = fmaf(Cm[tid][k], cjs[k], cd);
            float e = (Lj - cd) / djs * msk[tid];
            Cm[tid][t] = e;
            D[tid] -= e * e;
        }
        __syncthreads();
        if (tid == 0) {
            int Jn = argmax_logDm(D, msk);
            Jsh = Jn; msk[Jn] = 0.0f; sel[t] = Jn;
        }
        __syncthreads();
    }
    if (tid == 0) {
        for (int i = 1; i < MS; i++) {          // insertion sort ascending
            int key = sel[i], j = i - 1;
            while (j >= 0 && sel[j] > key) { sel[j+1] = sel[j]; j--; }
            sel[j+1] = key;
        }
        for (int k = 0; k < MS; k++) g_mu[b*MS + k] = sel[k];
    }
}

// ---------------- gaussian mixture -> softmax(dist) -> KL partial ----------
__global__ void distkl_k()
{
    const int b = blockIdx.x, tid = threadIdx.x;   // 256 threads, 8 s-values each
    __shared__ float red[256];
    int mus[MS];
    #pragma unroll
    for (int k = 0; k < MS; k++) mus[k] = g_mu[b*MS + k];

    float g[8];
    float mx = -CUDART_INF_F;
    #pragma unroll
    for (int i = 0; i < 8; i++) {
        const int s = tid + i*256;
        float acc = 0.0f;
        #pragma unroll
        for (int k = 0; k < MS; k++) {
            float z = (float)s - (float)mus[k];
            acc += expf(-z*z * (1.0f/18.0f));        // 2*sigma^2 = 18
        }
        acc *= 0.13298076013381091f;                 // 1/(sqrt(2pi)*3)
        g[i] = acc; mx = fmaxf(mx, acc);
    }
    red[tid] = mx; __syncthreads();
    for (int s = 128; s > 0; s >>= 1) { if (tid < s) red[tid] = fmaxf(red[tid], red[tid+s]); __syncthreads(); }
    mx = red[0]; __syncthreads();
    float sum = 0.0f;
    #pragma unroll
    for (int i = 0; i < 8; i++) { g[i] = expf(g[i] - mx); sum += g[i]; }
    red[tid] = sum; __syncthreads();
    for (int s = 128; s > 0; s >>= 1) { if (tid < s) red[tid] += red[tid+s]; __syncthreads(); }
    const float inv = 1.0f / red[0];
    __syncthreads();

    float kl = 0.0f;
    #pragma unroll
    for (int i = 0; i < 8; i++) {
        const int s = tid + i*256;
        float xm = g_xmean[b*Sc + s];
        kl += xm * (logf(xm) - g[i] * inv);
    }
    red[tid] = kl; __syncthreads();
    for (int s = 128; s > 0; s >>= 1) { if (tid < s) red[tid] += red[tid+s]; __syncthreads(); }
    if (tid == 0) atomicAdd(&g_kl, red[0]);
}

// ---------------- launch ----------------------------------------------------
extern "C" void kernel_launch(void* const* d_in, const int* in_sizes, int n_in,
                              void* d_out, int out_size)
{
    const float* x  = (const float*)d_in[0];
    const float* te = (const float*)d_in[1];
    const float* ek = (const float*)d_in[2];   // [B,E,S]
    const float* ev = (const float*)d_in[3];   // [B,S,E]
    const float* Wi = (const float*)d_in[4];   // [E,C]
    const float* bi = (const float*)d_in[5];
    const float* Wo = (const float*)d_in[6];   // [C,E]
    const float* bo = (const float*)d_in[7];

    float* out  = (float*)d_out;                              // [B,T,C]
    float* attn = out + (size_t)Bc * Tc * Cc;                 // [B,T,S]
    float* klp  = attn + (size_t)Bc * Tc * Sc;                // scalar

    float* hbuf = nullptr;
    cudaGetSymbolAddress((void**)&hbuf, g_h);
    __half *hf, *ekf, *evf, *af;
    cudaGetSymbolAddress((void**)&hf,  g_hf);
    cudaGetSymbolAddress((void**)&ekf, g_ekf);
    cudaGetSymbolAddress((void**)&evf, g_evf);
    cudaGetSymbolAddress((void**)&af,  g_af);

    cudaFuncSetAttribute(gemm_nn_fp16, cudaFuncAttributeMaxDynamicSharedMemorySize, NNF_SMEM);

    const float SQ05 = 0.70710678118654752f;
    const float SQS  = 45.25483399593904f;    // s*sqrt(1/s), s=2048

    // converts first (launch order kept stable for ncu slot)
    const int nEK4 = Bc * Ec * Sc / 4;  // per float4
    convert_f16<<<nEK4 / 256, 256>>>((const float4*)ek, (__half2*)ekf);
    convert_f16<<<nEK4 / 256, 256>>>((const float4*)ev, (__half2*)evf);

    // h = (x @ W_in^T + b_in + te) * sqrt(0.5)  -> fp16
    gemm_nt_h<<<dim3(Ec/64, (Bc*Tc)/128), 256>>>(x, Wi, bi, te, hf, Bc*Tc, Ec, Cc, SQ05);

    // scores = h @ enc_keys (fp16, fp32 acc), write into attn region
    gemm_nn_fp16<<<dim3(Sc/64, Tc/128, Bc), 256, NNF_SMEM>>>(
        hf, ekf, attn, Tc, Sc, Ec,
        (long long)Tc*Ec, (long long)Ec*Sc, (long long)Tc*Sc, 1.0f);

    // attn = softmax(scores) in place + fp16 copy
    softmax_f16<<<Bc*Tc, 256>>>(attn, af);

    // x_mean
    xmean_k<<<dim3(Sc/256, Bc), 256>>>(attn);

    // out1 = attn @ enc_values * sqrt(S)  (fp16, fp32 out into g_h)
    gemm_nn_fp16<<<dim3(Ec/64, Tc/128, Bc), 256, NNF_SMEM>>>(
        af, evf, hbuf, Tc, Ec, Sc,
        (long long)Tc*Sc, (long long)Sc*Ec, (long long)Tc*Ec, SQS);

    // out = (out1 @ W_out^T + b_out + x) * sqrt(0.5)
    gemm_nt_tc<<<dim3(Cc/64, (Bc*Tc)/128), 256>>>(hbuf, Wo, bo, x, out, Bc*Tc, Cc, Ec, SQ05);

    // DPP side path
    init_k<<<1, 1>>>();
    norm_aa_k<<<Bc, 256>>>(ev);
    L_k<<<dim3(Bc, NSEL), 128>>>(ev);
    bfgm_k<<<Bc, 128>>>();
    distkl_k<<<Bc, 256>>>();
    final_k<<<1, 1>>>(klp);
}

// round 11
// speedup vs baseline: 1.4974x; 1.4974x over previous
#include <cuda_runtime.h>
#include <cuda_fp16.h>
#include <math_constants.h>
#include <math.h>
#include <stdint.h>

#define Bc 16
#define Tc 1024
#define Sc 2048
#define Cc 256
#define Ec 256
#define NSEL 103     // ceil(2048/20)
#define MS 20
#define STRIDEc 20

// ---------------- scratch (device globals; no allocation allowed) ----------
__device__ float g_h[Bc*Tc*Ec];                 // out1 (fp32)
__device__ __half g_hf[Bc*Tc*Ec];               // h (fp16)
__device__ __half g_ekf[Bc*Ec*Sc];              // enc_keys fp16
__device__ __half g_evf[Bc*Sc*Ec];              // enc_values fp16
__device__ __half g_af[(size_t)Bc*Tc*Sc];       // attn fp16
__device__ float g_xmean[Bc*Sc];
__device__ float g_invn[Bc*NSEL];
__device__ float g_aa[Bc*NSEL];
__device__ float g_L[Bc*NSEL*NSEL];
__device__ int   g_mu[Bc*MS];
__device__ float g_kl;

// ---------------- small init / final ---------------------------------------
__global__ void init_k() { g_kl = 0.0f; }
__global__ void final_k(float* klout) { klout[0] = -g_kl; }

// ---------------- tf32 split (bitmask) for the weight GEMMs -----------------
__device__ __forceinline__ void split_tf32(float x, uint32_t& hi, uint32_t& lo)
{
    uint32_t xb = __float_as_uint(x);
    uint32_t h  = xb & 0xFFFFE000u;
    hi = h;
    lo = __float_as_uint(x - __uint_as_float(h));
}

#define MMA_TF32(c, a, b) \
    asm volatile("mma.sync.aligned.m16n8k8.row.col.f32.tf32.tf32.f32 " \
        "{%0,%1,%2,%3}, {%4,%5,%6,%7}, {%8,%9}, {%0,%1,%2,%3};" \
        : "+f"((c)[0]), "+f"((c)[1]), "+f"((c)[2]), "+f"((c)[3]) \
        : "r"((a)[0]), "r"((a)[1]), "r"((a)[2]), "r"((a)[3]), \
          "r"((b)[0]), "r"((b)[1]))

#define MMA_FP16(c, a, b) \
    asm volatile("mma.sync.aligned.m16n8k16.row.col.f32.f16.f16.f32 " \
        "{%0,%1,%2,%3}, {%4,%5,%6,%7}, {%8,%9}, {%0,%1,%2,%3};" \
        : "+f"((c)[0]), "+f"((c)[1]), "+f"((c)[2]), "+f"((c)[3]) \
        : "r"((a)[0]), "r"((a)[1]), "r"((a)[2]), "r"((a)[3]), \
          "r"((b)[0]), "r"((b)[1]))

#define LDSM4(r, addr) \
    asm volatile("ldmatrix.sync.aligned.m8n8.x4.shared.b16 {%0,%1,%2,%3}, [%4];" \
        : "=r"((r)[0]), "=r"((r)[1]), "=r"((r)[2]), "=r"((r)[3]) : "r"(addr))

#define LDSM4T(r, addr) \
    asm volatile("ldmatrix.sync.aligned.m8n8.x4.trans.shared.b16 {%0,%1,%2,%3}, [%4];" \
        : "=r"((r)[0]), "=r"((r)[1]), "=r"((r)[2]), "=r"((r)[3]) : "r"(addr))

__device__ __forceinline__ void cpa16(void* smem_dst, const void* gsrc)
{
    uint32_t d = (uint32_t)__cvta_generic_to_shared(smem_dst);
    asm volatile("cp.async.cg.shared.global [%0], [%1], 16;" :: "r"(d), "l"(gsrc));
}
__device__ __forceinline__ void cpa16s(uint32_t d, const void* gsrc)
{
    asm volatile("cp.async.cg.shared.global [%0], [%1], 16;" :: "r"(d), "l"(gsrc));
}
__device__ __forceinline__ void cpa_commit() { asm volatile("cp.async.commit_group;"); }
__device__ __forceinline__ void cpa_wait0()  { asm volatile("cp.async.wait_group 0;"); }
__device__ __forceinline__ void cpa_wait1()  { asm volatile("cp.async.wait_group 1;"); }
__device__ __forceinline__ void cpa_wait2()  { asm volatile("cp.async.wait_group 2;"); }

// ============================================================================
// Batched NN GEMM, single fp16, fp32 accumulate:  C = alpha * A[M,K] @ B[K,N]
// BM=128 BN=64 BK=32, 256 threads (8 warps: 4 in M x 2 in N), warp 32x32.
// 6-stage cp.async pipeline, ONE __syncthreads per k-iteration PAIR (depth-4
// prefetch) so warps can drift two iterations and overlap LSU/tensor phases.
// ============================================================================
#define NNF_A 0
#define NNF_B 10240
#define NNF_BUF 14848
#define NNF_STAGES 6
#define NNF_SMEM (NNF_STAGES*NNF_BUF)

__global__ __launch_bounds__(256, 2)
void gemm_nn_fp16(const __half* __restrict__ A, const __half* __restrict__ B,
                  float* __restrict__ C, int M, int N, int K,
                  long long sA, long long sB, long long sC, float alpha)
{
    extern __shared__ char smdyn[];
    const int bz = blockIdx.z;
    A += (size_t)bz * sA; B += (size_t)bz * sB; C += (size_t)bz * sC;
    const int m0 = blockIdx.y * 128, n0 = blockIdx.x * 64;
    const int tid = threadIdx.x, lane = tid & 31, wid = tid >> 5;
    const int wm = (wid & 3) * 32, wn = (wid >> 2) * 32;
    const int g = lane >> 2, t = lane & 3;
    const uint32_t sbase = (uint32_t)__cvta_generic_to_shared(smdyn);

    float c[2][4][4] = {};
    const int S = K / 32;   // S is even (K=256 or 2048)

    auto issue = [&](int kt) {
        const uint32_t base = sbase + (kt % NNF_STAGES) * NNF_BUF;
        const int k0 = kt * 32;
        #pragma unroll
        for (int j = 0; j < 2; j++) {
            int ch = tid + j * 256, row = ch >> 2, cc = ch & 3;
            cpa16s(base + NNF_A + row * 80 + cc * 16, A + (size_t)(m0 + row) * K + k0 + cc * 8);
        }
        {
            int row = tid >> 3, cc = tid & 7;
            cpa16s(base + NNF_B + row * 144 + cc * 16, B + (size_t)(k0 + row) * N + n0 + cc * 8);
        }
        cpa_commit();
    };

    auto compute = [&](int s) {
        const uint32_t base = sbase + (s % NNF_STAGES) * NNF_BUF;
        #pragma unroll
        for (int ks = 0; ks < 2; ks++) {
            uint32_t a[2][4];
            #pragma unroll
            for (int mt = 0; mt < 2; mt++) {
                uint32_t addr = base + NNF_A
                    + (uint32_t)(wm + mt * 16 + (lane & 15)) * 80
                    + (uint32_t)(ks * 32 + (lane >> 4) * 16);
                LDSM4(a[mt], addr);
            }
            uint32_t b[2][4];
            #pragma unroll
            for (int bt = 0; bt < 2; bt++) {
                uint32_t addr = base + NNF_B
                    + (uint32_t)(ks * 16 + (lane & 15)) * 144
                    + (uint32_t)((wn + bt * 16) * 2 + (lane >> 4) * 16);
                LDSM4T(b[bt], addr);
            }
            #pragma unroll
            for (int mt = 0; mt < 2; mt++)
                #pragma unroll
                for (int nt = 0; nt < 4; nt++)
                    MMA_FP16(c[mt][nt], a[mt], (&b[nt >> 1][(nt & 1) * 2]));
        }
    };

    issue(0); issue(1); issue(2); issue(3);
    for (int s = 0; s < S; s += 2) {
        if (s + 2 < S) cpa_wait2(); else cpa_wait0();
        __syncthreads();
        if (s + 4 < S) issue(s + 4);
        if (s + 5 < S) issue(s + 5);
        compute(s);
        compute(s + 1);
    }

    #pragma unroll
    for (int mt = 0; mt < 2; mt++)
        #pragma unroll
        for (int nt = 0; nt < 4; nt++) {
            int row = m0 + wm + mt * 16 + g;
            int col = n0 + wn + nt * 8 + 2 * t;
            float2 v0 = make_float2(alpha * c[mt][nt][0], alpha * c[mt][nt][1]);
            float2 v1 = make_float2(alpha * c[mt][nt][2], alpha * c[mt][nt][3]);
            *(float2*)&C[(size_t)row * N + col]       = v0;
            *(float2*)&C[(size_t)(row + 8) * N + col] = v1;
        }
}

// ============================================================================
// convert: fp32 -> fp16 (vectorized)
// ============================================================================
__global__ void convert_f16(const float4* __restrict__ src, __half2* __restrict__ h2)
{
    const int i = blockIdx.x * 256 + threadIdx.x;
    float4 v = src[i];
    h2[2*i]     = __floats2half2_rn(v.x, v.y);
    h2[2*i + 1] = __floats2half2_rn(v.z, v.w);
}

// ============================================================================
// NT GEMM (tf32 split) producing fp16 h: h = (A @ W^T + bias + add)*scale
// ============================================================================
__global__ __launch_bounds__(256, 2)
void gemm_nt_h(const float* __restrict__ A, const float* __restrict__ W,
               const float* __restrict__ bias, const float* __restrict__ add,
               __half* __restrict__ outf, int M, int N, int K, float scale)
{
    const int m0 = blockIdx.y * 128, n0 = blockIdx.x * 64;
    const int tid = threadIdx.x, lane = tid & 31, wid = tid >> 5;
    const int wm = (wid & 3) * 32, wn = (wid >> 2) * 32;
    const int g = lane >> 2, t = lane & 3;

    __shared__ float As[2][128][20];
    __shared__ float Ws[2][64][20];

    float c[2][4][4] = {};
    const int S = K / 16;

    auto issue = [&](int s, int buf) {
        const int k0 = s * 16;
        #pragma unroll
        for (int j = 0; j < 2; j++) {
            int ch = tid + j * 256;
            int row = ch >> 2, kc = ch & 3;
            cpa16(&As[buf][row][kc * 4], A + (size_t)(m0 + row) * K + k0 + kc * 4);
        }
        int wrow = tid >> 2, wkc = tid & 3;
        cpa16(&Ws[buf][wrow][wkc * 4], W + (size_t)(n0 + wrow) * K + k0 + wkc * 4);
        cpa_commit();
    };

    issue(0, 0);
    for (int s = 0; s < S; s++) {
        if (s + 1 < S) { issue(s + 1, (s + 1) & 1); cpa_wait1(); }
        else cpa_wait0();
        __syncthreads();
        const int buf = s & 1;
        #pragma unroll
        for (int kf = 0; kf < 2; kf++) {
            uint32_t ah[2][4], al[2][4];
            #pragma unroll
            for (int mt = 0; mt < 2; mt++) {
                int mr = wm + mt * 16 + g;
                split_tf32(As[buf][mr    ][kf*8 + t],     ah[mt][0], al[mt][0]);
                split_tf32(As[buf][mr + 8][kf*8 + t],     ah[mt][1], al[mt][1]);
                split_tf32(As[buf][mr    ][kf*8 + t + 4], ah[mt][2], al[mt][2]);
                split_tf32(As[buf][mr + 8][kf*8 + t + 4], ah[mt][3], al[mt][3]);
            }
            uint32_t bh[4][2], bl[4][2];
            #pragma unroll
            for (int nt = 0; nt < 4; nt++) {
                int nr = wn + nt * 8 + g;
                split_tf32(Ws[buf][nr][kf*8 + t],     bh[nt][0], bl[nt][0]);
                split_tf32(Ws[buf][nr][kf*8 + t + 4], bh[nt][1], bl[nt][1]);
            }
            #pragma unroll
            for (int mt = 0; mt < 2; mt++)
                #pragma unroll
                for (int nt = 0; nt < 4; nt++)
                    MMA_TF32(c[mt][nt], ah[mt], bh[nt]);
            #pragma unroll
            for (int mt = 0; mt < 2; mt++)
                #pragma unroll
                for (int nt = 0; nt < 4; nt++)
                    MMA_TF32(c[mt][nt], ah[mt], bl[nt]);
            #pragma unroll
            for (int mt = 0; mt < 2; mt++)
                #pragma unroll
                for (int nt = 0; nt < 4; nt++)
                    MMA_TF32(c[mt][nt], al[mt], bh[nt]);
        }
        __syncthreads();
    }

    #pragma unroll
    for (int mt = 0; mt < 2; mt++)
        #pragma unroll
        for (int nt = 0; nt < 4; nt++) {
            int row = m0 + wm + mt * 16 + g;
            int col = n0 + wn + nt * 8 + 2 * t;
            float2 bv = *(const float2*)&bias[col];
            size_t i0 = (size_t)row * N + col;
            size_t i1 = (size_t)(row + 8) * N + col;
            float2 d0 = *(const float2*)&add[i0];
            float2 d1 = *(const float2*)&add[i1];
            float v00 = (c[mt][nt][0] + bv.x + d0.x) * scale;
            float v01 = (c[mt][nt][1] + bv.y + d0.y) * scale;
            float v10 = (c[mt][nt][2] + bv.x + d1.x) * scale;
            float v11 = (c[mt][nt][3] + bv.y + d1.y) * scale;
            *(__half2*)&outf[i0] = __floats2half2_rn(v00, v01);
            *(__half2*)&outf[i1] = __floats2half2_rn(v10, v11);
        }
}

// ============================================================================
// NT GEMM with fp32 epilogue (final output): out = (A @ W^T + bias + add)*scale
// ============================================================================
__global__ __launch_bounds__(256, 2)
void gemm_nt_tc(const float* __restrict__ A, const float* __restrict__ W,
                const float* __restrict__ bias, const float* __restrict__ add,
                float* __restrict__ out, int M, int N, int K, float scale)
{
    const int m0 = blockIdx.y * 128, n0 = blockIdx.x * 64;
    const int tid = threadIdx.x, lane = tid & 31, wid = tid >> 5;
    const int wm = (wid & 3) * 32, wn = (wid >> 2) * 32;
    const int g = lane >> 2, t = lane & 3;

    __shared__ float As[2][128][20];
    __shared__ float Ws[2][64][20];

    float c[2][4][4] = {};
    const int S = K / 16;

    auto issue = [&](int s, int buf) {
        const int k0 = s * 16;
        #pragma unroll
        for (int j = 0; j < 2; j++) {
            int ch = tid + j * 256;
            int row = ch >> 2, kc = ch & 3;
            cpa16(&As[buf][row][kc * 4], A + (size_t)(m0 + row) * K + k0 + kc * 4);
        }
        int wrow = tid >> 2, wkc = tid & 3;
        cpa16(&Ws[buf][wrow][wkc * 4], W + (size_t)(n0 + wrow) * K + k0 + wkc * 4);
        cpa_commit();
    };

    issue(0, 0);
    for (int s = 0; s < S; s++) {
        if (s + 1 < S) { issue(s + 1, (s + 1) & 1); cpa_wait1(); }
        else cpa_wait0();
        __syncthreads();
        const int buf = s & 1;
        #pragma unroll
        for (int kf = 0; kf < 2; kf++) {
            uint32_t ah[2][4], al[2][4];
            #pragma unroll
            for (int mt = 0; mt < 2; mt++) {
                int mr = wm + mt * 16 + g;
                split_tf32(As[buf][mr    ][kf*8 + t],     ah[mt][0], al[mt][0]);
                split_tf32(As[buf][mr + 8][kf*8 + t],     ah[mt][1], al[mt][1]);
                split_tf32(As[buf][mr    ][kf*8 + t + 4], ah[mt][2], al[mt][2]);
                split_tf32(As[buf][mr + 8][kf*8 + t + 4], ah[mt][3], al[mt][3]);
            }
            uint32_t bh[4][2], bl[4][2];
            #pragma unroll
            for (int nt = 0; nt < 4; nt++) {
                int nr = wn + nt * 8 + g;
                split_tf32(Ws[buf][nr][kf*8 + t],     bh[nt][0], bl[nt][0]);
                split_tf32(Ws[buf][nr][kf*8 + t + 4], bh[nt][1], bl[nt][1]);
            }
            #pragma unroll
            for (int mt = 0; mt < 2; mt++)
                #pragma unroll
                for (int nt = 0; nt < 4; nt++)
                    MMA_TF32(c[mt][nt], ah[mt], bh[nt]);
            #pragma unroll
            for (int mt = 0; mt < 2; mt++)
                #pragma unroll
                for (int nt = 0; nt < 4; nt++)
                    MMA_TF32(c[mt][nt], ah[mt], bl[nt]);
            #pragma unroll
            for (int mt = 0; mt < 2; mt++)
                #pragma unroll
                for (int nt = 0; nt < 4; nt++)
                    MMA_TF32(c[mt][nt], al[mt], bh[nt]);
        }
        __syncthreads();
    }

    #pragma unroll
    for (int mt = 0; mt < 2; mt++)
        #pragma unroll
        for (int nt = 0; nt < 4; nt++) {
            int row = m0 + wm + mt * 16 + g;
            int col = n0 + wn + nt * 8 + 2 * t;
            float2 bv = *(const float2*)&bias[col];
            size_t i0 = (size_t)row * N + col;
            size_t i1 = (size_t)(row + 8) * N + col;
            float2 d0 = *(const float2*)&add[i0];
            float2 d1 = *(const float2*)&add[i1];
            float2 v0 = make_float2((c[mt][nt][0] + bv.x + d0.x) * scale,
                                    (c[mt][nt][1] + bv.y + d0.y) * scale);
            float2 v1 = make_float2((c[mt][nt][2] + bv.x + d1.x) * scale,
                                    (c[mt][nt][3] + bv.y + d1.y) * scale);
            *(float2*)&out[i0] = v0;
            *(float2*)&out[i1] = v1;
        }
}

// ---------------- row softmax (in place) + fp16 copy ------------------------
__global__ void softmax_f16(float* __restrict__ attn, __half* __restrict__ af)
{
    const size_t row = blockIdx.x;
    float* p = attn + row * (size_t)Sc;
    __half* pf = af + row * (size_t)Sc;
    const int tid = threadIdx.x;   // 256 threads, 8 elems each
    __shared__ float red[256];
    float v[8];
    float mx = -CUDART_INF_F;
    #pragma unroll
    for (int i = 0; i < 8; i++) { v[i] = p[tid + i*256]; mx = fmaxf(mx, v[i]); }
    red[tid] = mx; __syncthreads();
    for (int s = 128; s > 0; s >>= 1) { if (tid < s) red[tid] = fmaxf(red[tid], red[tid+s]); __syncthreads(); }
    mx = red[0]; __syncthreads();
    float sum = 0.0f;
    #pragma unroll
    for (int i = 0; i < 8; i++) { v[i] = __expf(v[i] - mx); sum += v[i]; }
    red[tid] = sum; __syncthreads();
    for (int s = 128; s > 0; s >>= 1) { if (tid < s) red[tid] += red[tid+s]; __syncthreads(); }
    const float inv = 1.0f / red[0];
    #pragma unroll
    for (int i = 0; i < 8; i++) {
        float a = v[i] * inv;
        p[tid + i*256] = a;
        pf[tid + i*256] = __float2half_rn(a);
    }
}

// ---------------- x_mean[b][s] = mean_t attn[b][t][s] -----------------------
__global__ void xmean_k(const float* __restrict__ attn)
{
    const int b = blockIdx.y;
    const int s = blockIdx.x * 256 + threadIdx.x;
    const float* p = attn + (size_t)b * Tc * Sc + s;
    float sum = 0.0f;
    for (int t = 0; t < Tc; t++) sum += p[(size_t)t * Sc];
    g_xmean[b * Sc + s] = sum * (1.0f / Tc);
}

// ---------------- row inv-norms of strided enc_values + aa -----------------
__global__ void norm_aa_k(const float* __restrict__ V)
{
    const int b = blockIdx.x;
    const int w = threadIdx.x >> 5, lane = threadIdx.x & 31;
    for (int n = w; n < NSEL; n += 8) {
        const float* row = V + ((size_t)b * Sc + (size_t)n * STRIDEc) * Ec;
        float s = 0.0f;
        for (int e = lane; e < Ec; e += 32) { float x = row[e]; s = fmaf(x, x, s); }
        #pragma unroll
        for (int o = 16; o; o >>= 1) s += __shfl_down_sync(0xffffffffu, s, o);
        if (lane == 0) {
            g_invn[b * NSEL + n] = rsqrtf(s);
            g_aa[b * NSEL + n]   = g_xmean[b * Sc + n * STRIDEc];
        }
    }
}

// ---------------- L[b][n][m] = aa_n aa_m * <v_n,v_m>/(|v_n||v_m|) ----------
__global__ void L_k(const float* __restrict__ V)
{
    const int b = blockIdx.x, n = blockIdx.y;
    __shared__ float vn[Ec];
    const float* rn = V + ((size_t)b * Sc + (size_t)n * STRIDEc) * Ec;
    for (int e = threadIdx.x; e < Ec; e += 128) vn[e] = rn[e];
    __syncthreads();
    const int m = threadIdx.x;
    if (m < NSEL) {
        const float* rm = V + ((size_t)b * Sc + (size_t)m * STRIDEc) * Ec;
        float d = 0.0f;
        for (int e = 0; e < Ec; e++) d = fmaf(vn[e], rm[e], d);
        float val = d * g_invn[b*NSEL + n] * g_invn[b*NSEL + m]
                      * g_aa[b*NSEL + n]   * g_aa[b*NSEL + m];
        g_L[((size_t)b * NSEL + n) * NSEL + m] = val;
    }
}

// numpy-style argmax of logf(D[n]*mask[n]): first NaN wins; strict > keeps first max
__device__ __forceinline__ int argmax_logDm(const float* D, const float* msk)
{
    int J = 0; float best = -CUDART_INF_F; bool done = false;
    for (int n = 0; n < NSEL && !done; n++) {
        float v = logf(D[n] * msk[n]);
        if (isnan(v)) { J = n; done = true; }
        else if (v > best) { best = v; J = n; }
    }
    return J;
}

// ---------------- greedy bfgm selection (sequential, tiny) -----------------
__global__ void bfgm_k()
{
    const int b = blockIdx.x, tid = threadIdx.x;  // 128 threads
    __shared__ float Cm[NSEL][MS];
    __shared__ float D[NSEL], msk[NSEL], cjs[MS];
    __shared__ float djs;
    __shared__ int Jsh, sel[MS];
    const float* L = g_L + (size_t)b * NSEL * NSEL;

    if (tid < NSEL) {
        D[tid] = L[(size_t)tid * NSEL + tid];
        msk[tid] = 1.0f;
        #pragma unroll
        for (int k = 0; k < MS; k++) Cm[tid][k] = 0.0f;
    }
    __syncthreads();
    if (tid == 0) {
        int J = argmax_logDm(D, msk);
        Jsh = J; msk[J] = 0.0f; sel[0] = J;
    }
    __syncthreads();

    for (int t = 1; t < MS; t++) {
        const int J = Jsh;
        if (tid < MS) cjs[tid] = Cm[J][tid];
        if (tid == 0) djs = D[J];
        __syncthreads();
        if (tid < NSEL) {
            float Lj = L[(size_t)J * NSEL + tid];
            float cd = 0.0f;
            #pragma unroll
            for (int k = 0; k < MS; k++) cd = fmaf(Cm[tid][k], cjs[k], cd);
            float e = (Lj - cd) / djs * msk[tid];
            Cm[tid][t] = e;
            D[tid] -= e * e;
        }
        __syncthreads();
        if (tid == 0) {
            int Jn = argmax_logDm(D, msk);
            Jsh = Jn; msk[Jn] = 0.0f; sel[t] = Jn;
        }
        __syncthreads();
    }
    if (tid == 0) {
        for (int i = 1; i < MS; i++) {          // insertion sort ascending
            int key = sel[i], j = i - 1;
            while (j >= 0 && sel[j] > key) { sel[j+1] = sel[j]; j--; }
            sel[j+1] = key;
        }
        for (int k = 0; k < MS; k++) g_mu[b*MS + k] = sel[k];
    }
}

// ---------------- gaussian mixture -> softmax(dist) -> KL partial ----------
__global__ void distkl_k()
{
    const int b = blockIdx.x, tid = threadIdx.x;   // 256 threads, 8 s-values each
    __shared__ float red[256];
    int mus[MS];
    #pragma unroll
    for (int k = 0; k < MS; k++) mus[k] = g_mu[b*MS + k];

    float g[8];
    float mx = -CUDART_INF_F;
    #pragma unroll
    for (int i = 0; i < 8; i++) {
        const int s = tid + i*256;
        float acc = 0.0f;
        #pragma unroll
        for (int k = 0; k < MS; k++) {
            float z = (float)s - (float)mus[k];
            acc += expf(-z*z * (1.0f/18.0f));        // 2*sigma^2 = 18
        }
        acc *= 0.13298076013381091f;                 // 1/(sqrt(2pi)*3)
        g[i] = acc; mx = fmaxf(mx, acc);
    }
    red[tid] = mx; __syncthreads();
    for (int s = 128; s > 0; s >>= 1) { if (tid < s) red[tid] = fmaxf(red[tid], red[tid+s]); __syncthreads(); }
    mx = red[0]; __syncthreads();
    float sum = 0.0f;
    #pragma unroll
    for (int i = 0; i < 8; i++) { g[i] = expf(g[i] - mx); sum += g[i]; }
    red[tid] = sum; __syncthreads();
    for (int s = 128; s > 0; s >>= 1) { if (tid < s) red[tid] += red[tid+s]; __syncthreads(); }
    const float inv = 1.0f / red[0];
    __syncthreads();

    float kl = 0.0f;
    #pragma unroll
    for (int i = 0; i < 8; i++) {
        const int s = tid + i*256;
        float xm = g_xmean[b*Sc + s];
        kl += xm * (logf(xm) - g[i] * inv);
    }
    red[tid] = kl; __syncthreads();
    for (int s = 128; s > 0; s >>= 1) { if (tid < s) red[tid] += red[tid+s]; __syncthreads(); }
    if (tid == 0) atomicAdd(&g_kl, red[0]);
}

// ---------------- launch ----------------------------------------------------
extern "C" void kernel_launch(void* const* d_in, const int* in_sizes, int n_in,
                              void* d_out, int out_size)
{
    const float* x  = (const float*)d_in[0];
    const float* te = (const float*)d_in[1];
    const float* ek = (const float*)d_in[2];   // [B,E,S]
    const float* ev = (const float*)d_in[3];   // [B,S,E]
    const float* Wi = (const float*)d_in[4];   // [E,C]
    const float* bi = (const float*)d_in[5];
    const float* Wo = (const float*)d_in[6];   // [C,E]
    const float* bo = (const float*)d_in[7];

    float* out  = (float*)d_out;                              // [B,T,C]
    float* attn = out + (size_t)Bc * Tc * Cc;                 // [B,T,S]
    float* klp  = attn + (size_t)Bc * Tc * Sc;                // scalar

    float* hbuf = nullptr;
    cudaGetSymbolAddress((void**)&hbuf, g_h);
    __half *hf, *ekf, *evf, *af;
    cudaGetSymbolAddress((void**)&hf,  g_hf);
    cudaGetSymbolAddress((void**)&ekf, g_ekf);
    cudaGetSymbolAddress((void**)&evf, g_evf);
    cudaGetSymbolAddress((void**)&af,  g_af);

    cudaFuncSetAttribute(gemm_nn_fp16, cudaFuncAttributeMaxDynamicSharedMemorySize, NNF_SMEM);

    const float SQ05 = 0.70710678118654752f;
    const float SQS  = 45.25483399593904f;    // s*sqrt(1/s), s=2048

    // converts first (launch order kept stable for ncu slot)
    const int nEK4 = Bc * Ec * Sc / 4;  // per float4
    convert_f16<<<nEK4 / 256, 256>>>((const float4*)ek, (__half2*)ekf);
    convert_f16<<<nEK4 / 256, 256>>>((const float4*)ev, (__half2*)evf);

    // h = (x @ W_in^T + b_in + te) * sqrt(0.5)  -> fp16
    gemm_nt_h<<<dim3(Ec/64, (Bc*Tc)/128), 256>>>(x, Wi, bi, te, hf, Bc*Tc, Ec, Cc, SQ05);

    // scores = h @ enc_keys (fp16, fp32 acc), write into attn region
    gemm_nn_fp16<<<dim3(Sc/64, Tc/128, Bc), 256, NNF_SMEM>>>(
        hf, ekf, attn, Tc, Sc, Ec,
        (long long)Tc*Ec, (long long)Ec*Sc, (long long)Tc*Sc, 1.0f);

    // attn = softmax(scores) in place + fp16 copy
    softmax_f16<<<Bc*Tc, 256>>>(attn, af);

    // x_mean
    xmean_k<<<dim3(Sc/256, Bc), 256>>>(attn);

    // out1 = attn @ enc_values * sqrt(S)  (fp16, fp32 out into g_h)
    gemm_nn_fp16<<<dim3(Ec/64, Tc/128, Bc), 256, NNF_SMEM>>>(
        af, evf, hbuf, Tc, Ec, Sc,
        (long long)Tc*Sc, (long long)Sc*Ec, (long long)Tc*Ec, SQS);

    // out = (out1 @ W_out^T + b_out + x) * sqrt(0.5)
    gemm_nt_tc<<<dim3(Cc/64, (Bc*Tc)/128), 256>>>(hbuf, Wo, bo, x, out, Bc*Tc, Cc, Ec, SQ05);

    // DPP side path
    init_k<<<1, 1>>>();
    norm_aa_k<<<Bc, 256>>>(ev);
    L_k<<<dim3(Bc, NSEL), 128>>>(ev);
    bfgm_k<<<Bc, 128>>>();
    distkl_k<<<Bc, 256>>>();
    final_k<<<1, 1>>>(klp);
}

// round 12
// speedup vs baseline: 1.6270x; 1.0865x over previous
#include <cuda_runtime.h>
#include <cuda_fp16.h>
#include <math_constants.h>
#include <math.h>
#include <stdint.h>

#define Bc 16
#define Tc 1024
#define Sc 2048
#define Cc 256
#define Ec 256
#define NSEL 103     // ceil(2048/20)
#define MS 20
#define STRIDEc 20

// ---------------- scratch (device globals; no allocation allowed) ----------
__device__ __half g_xf[Bc*Tc*Cc];               // x fp16
__device__ __half g_hf[Bc*Tc*Ec];               // h fp16
__device__ __half g_ekf[Bc*Ec*Sc];              // enc_keys fp16
__device__ __half g_evf[Bc*Sc*Ec];              // enc_values fp16
__device__ __half g_af[(size_t)Bc*Tc*Sc];       // attn fp16
__device__ __half g_o1f[Bc*Tc*Ec];              // out1 fp16
__device__ __half g_WiT[Cc*Ec];                 // Wi^T [C,E] fp16
__device__ __half g_WoT[Ec*Cc];                 // Wo^T [E,C] fp16
__device__ float g_xmean[Bc*Sc];
__device__ float g_invn[Bc*NSEL];
__device__ float g_aa[Bc*NSEL];
__device__ float g_L[Bc*NSEL*NSEL];
__device__ int   g_mu[Bc*MS];
__device__ float g_kl;

// ---------------- small init / final ---------------------------------------
__global__ void init_k() { g_kl = 0.0f; }
__global__ void final_k(float* klout) { klout[0] = -g_kl; }

#define MMA_FP16(c, a, b) \
    asm volatile("mma.sync.aligned.m16n8k16.row.col.f32.f16.f16.f32 " \
        "{%0,%1,%2,%3}, {%4,%5,%6,%7}, {%8,%9}, {%0,%1,%2,%3};" \
        : "+f"((c)[0]), "+f"((c)[1]), "+f"((c)[2]), "+f"((c)[3]) \
        : "r"((a)[0]), "r"((a)[1]), "r"((a)[2]), "r"((a)[3]), \
          "r"((b)[0]), "r"((b)[1]))

#define LDSM4(r, addr) \
    asm volatile("ldmatrix.sync.aligned.m8n8.x4.shared.b16 {%0,%1,%2,%3}, [%4];" \
        : "=r"((r)[0]), "=r"((r)[1]), "=r"((r)[2]), "=r"((r)[3]) : "r"(addr))

#define LDSM4T(r, addr) \
    asm volatile("ldmatrix.sync.aligned.m8n8.x4.trans.shared.b16 {%0,%1,%2,%3}, [%4];" \
        : "=r"((r)[0]), "=r"((r)[1]), "=r"((r)[2]), "=r"((r)[3]) : "r"(addr))

__device__ __forceinline__ void cpa16s(uint32_t d, const void* gsrc)
{
    asm volatile("cp.async.cg.shared.global [%0], [%1], 16;" :: "r"(d), "l"(gsrc));
}
__device__ __forceinline__ void cpa_commit() { asm volatile("cp.async.commit_group;"); }
__device__ __forceinline__ void cpa_wait0()  { asm volatile("cp.async.wait_group 0;"); }
__device__ __forceinline__ void cpa_wait2()  { asm volatile("cp.async.wait_group 2;"); }

// ============================================================================
// Shared fp16 NN GEMM core: acc = A[M,K] @ B[K,N] block tile (BM=128 BN=64
// BK=32), 256 thr (8 warps 4x2), 6-stage cp.async, 1 barrier per k-pair.
// ============================================================================
#define NNF_A 0
#define NNF_B 10240
#define NNF_BUF 14848
#define NNF_STAGES 6
#define NNF_SMEM (NNF_STAGES*NNF_BUF)

__device__ __forceinline__ void nn_core(
    const __half* __restrict__ A, const __half* __restrict__ B,
    int N, int K, int m0, int n0, float c[2][4][4], char* smdyn)
{
    const int tid = threadIdx.x, lane = tid & 31, wid = tid >> 5;
    const int wm = (wid & 3) * 32, wn = (wid >> 2) * 32;
    const uint32_t sbase = (uint32_t)__cvta_generic_to_shared(smdyn);
    const int S = K / 32;   // even for all our K (256, 2048)

    auto issue = [&](int kt) {
        const uint32_t base = sbase + (kt % NNF_STAGES) * NNF_BUF;
        const int k0 = kt * 32;
        #pragma unroll
        for (int j = 0; j < 2; j++) {
            int ch = tid + j * 256, row = ch >> 2, cc = ch & 3;
            cpa16s(base + NNF_A + row * 80 + cc * 16, A + (size_t)(m0 + row) * K + k0 + cc * 8);
        }
        {
            int row = tid >> 3, cc = tid & 7;
            cpa16s(base + NNF_B + row * 144 + cc * 16, B + (size_t)(k0 + row) * N + n0 + cc * 8);
        }
        cpa_commit();
    };

    auto compute = [&](int s) {
        const uint32_t base = sbase + (s % NNF_STAGES) * NNF_BUF;
        #pragma unroll
        for (int ks = 0; ks < 2; ks++) {
            uint32_t a[2][4];
            #pragma unroll
            for (int mt = 0; mt < 2; mt++) {
                uint32_t addr = base + NNF_A
                    + (uint32_t)(wm + mt * 16 + (lane & 15)) * 80
                    + (uint32_t)(ks * 32 + (lane >> 4) * 16);
                LDSM4(a[mt], addr);
            }
            uint32_t b[2][4];
            #pragma unroll
            for (int bt = 0; bt < 2; bt++) {
                uint32_t addr = base + NNF_B
                    + (uint32_t)(ks * 16 + (lane & 15)) * 144
                    + (uint32_t)((wn + bt * 16) * 2 + (lane >> 4) * 16);
                LDSM4T(b[bt], addr);
            }
            #pragma unroll
            for (int mt = 0; mt < 2; mt++)
                #pragma unroll
                for (int nt = 0; nt < 4; nt++)
                    MMA_FP16(c[mt][nt], a[mt], (&b[nt >> 1][(nt & 1) * 2]));
        }
    };

    issue(0); issue(1); issue(2); issue(3);
    for (int s = 0; s < S; s += 2) {
        if (s + 2 < S) cpa_wait2(); else cpa_wait0();
        __syncthreads();
        if (s + 4 < S) issue(s + 4);
        if (s + 5 < S) issue(s + 5);
        compute(s);
        compute(s + 1);
    }
}

// ---- scores: fp32 C = alpha * A@B (batched) --------------------------------
__global__ __launch_bounds__(256, 2)
void gemm_nn_fp16(const __half* __restrict__ A, const __half* __restrict__ B,
                  float* __restrict__ C, int N, int K,
                  long long sA, long long sB, long long sC, float alpha)
{
    extern __shared__ char smdyn[];
    const int bz = blockIdx.z;
    A += (size_t)bz * sA; B += (size_t)bz * sB; C += (size_t)bz * sC;
    const int m0 = blockIdx.y * 128, n0 = blockIdx.x * 64;
    const int lane = threadIdx.x & 31, wid = threadIdx.x >> 5;
    const int wm = (wid & 3) * 32, wn = (wid >> 2) * 32;
    const int g = lane >> 2, t = lane & 3;
    float c[2][4][4] = {};
    nn_core(A, B, N, K, m0, n0, c, smdyn);
    #pragma unroll
    for (int mt = 0; mt < 2; mt++)
        #pragma unroll
        for (int nt = 0; nt < 4; nt++) {
            int row = m0 + wm + mt * 16 + g;
            int col = n0 + wn + nt * 8 + 2 * t;
            *(float2*)&C[(size_t)row * N + col] =
                make_float2(alpha * c[mt][nt][0], alpha * c[mt][nt][1]);
            *(float2*)&C[(size_t)(row + 8) * N + col] =
                make_float2(alpha * c[mt][nt][2], alpha * c[mt][nt][3]);
        }
}

// ---- out1: fp16 C = alpha * A@B (batched) ----------------------------------
__global__ __launch_bounds__(256, 2)
void gemm_nn_f16o(const __half* __restrict__ A, const __half* __restrict__ B,
                  __half* __restrict__ C, int N, int K,
                  long long sA, long long sB, long long sC, float alpha)
{
    extern __shared__ char smdyn[];
    const int bz = blockIdx.z;
    A += (size_t)bz * sA; B += (size_t)bz * sB; C += (size_t)bz * sC;
    const int m0 = blockIdx.y * 128, n0 = blockIdx.x * 64;
    const int lane = threadIdx.x & 31, wid = threadIdx.x >> 5;
    const int wm = (wid & 3) * 32, wn = (wid >> 2) * 32;
    const int g = lane >> 2, t = lane & 3;
    float c[2][4][4] = {};
    nn_core(A, B, N, K, m0, n0, c, smdyn);
    #pragma unroll
    for (int mt = 0; mt < 2; mt++)
        #pragma unroll
        for (int nt = 0; nt < 4; nt++) {
            int row = m0 + wm + mt * 16 + g;
            int col = n0 + wn + nt * 8 + 2 * t;
            *(__half2*)&C[(size_t)row * N + col] =
                __floats2half2_rn(alpha * c[mt][nt][0], alpha * c[mt][nt][1]);
            *(__half2*)&C[(size_t)(row + 8) * N + col] =
                __floats2half2_rn(alpha * c[mt][nt][2], alpha * c[mt][nt][3]);
        }
}

// ---- h: fp16 C = (A@B + bias + add)*scale -----------------------------------
__global__ __launch_bounds__(256, 2)
void gemm_nn_epH(const __half* __restrict__ A, const __half* __restrict__ B,
                 const float* __restrict__ bias, const float* __restrict__ add,
                 __half* __restrict__ C, int N, int K, float scale)
{
    extern __shared__ char smdyn[];
    const int m0 = blockIdx.y * 128, n0 = blockIdx.x * 64;
    const int lane = threadIdx.x & 31, wid = threadIdx.x >> 5;
    const int wm = (wid & 3) * 32, wn = (wid >> 2) * 32;
    const int g = lane >> 2, t = lane & 3;
    float c[2][4][4] = {};
    nn_core(A, B, N, K, m0, n0, c, smdyn);
    #pragma unroll
    for (int mt = 0; mt < 2; mt++)
        #pragma unroll
        for (int nt = 0; nt < 4; nt++) {
            int row = m0 + wm + mt * 16 + g;
            int col = n0 + wn + nt * 8 + 2 * t;
            float2 bv = *(const float2*)&bias[col];
            size_t i0 = (size_t)row * N + col;
            size_t i1 = (size_t)(row + 8) * N + col;
            float2 d0 = *(const float2*)&add[i0];
            float2 d1 = *(const float2*)&add[i1];
            *(__half2*)&C[i0] = __floats2half2_rn((c[mt][nt][0] + bv.x + d0.x) * scale,
                                                  (c[mt][nt][1] + bv.y + d0.y) * scale);
            *(__half2*)&C[i1] = __floats2half2_rn((c[mt][nt][2] + bv.x + d1.x) * scale,
                                                  (c[mt][nt][3] + bv.y + d1.y) * scale);
        }
}

// ---- final out: fp32 C = (A@B + bias + add)*scale ---------------------------
__global__ __launch_bounds__(256, 2)
void gemm_nn_epF(const __half* __restrict__ A, const __half* __restrict__ B,
                 const float* __restrict__ bias, const float* __restrict__ add,
                 float* __restrict__ C, int N, int K, float scale)
{
    extern __shared__ char smdyn[];
    const int m0 = blockIdx.y * 128, n0 = blockIdx.x * 64;
    const int lane = threadIdx.x & 31, wid = threadIdx.x >> 5;
    const int wm = (wid & 3) * 32, wn = (wid >> 2) * 32;
    const int g = lane >> 2, t = lane & 3;
    float c[2][4][4] = {};
    nn_core(A, B, N, K, m0, n0, c, smdyn);
    #pragma unroll
    for (int mt = 0; mt < 2; mt++)
        #pragma unroll
        for (int nt = 0; nt < 4; nt++) {
            int row = m0 + wm + mt * 16 + g;
            int col = n0 + wn + nt * 8 + 2 * t;
            float2 bv = *(const float2*)&bias[col];
            size_t i0 = (size_t)row * N + col;
            size_t i1 = (size_t)(row + 8) * N + col;
            float2 d0 = *(const float2*)&add[i0];
            float2 d1 = *(const float2*)&add[i1];
            *(float2*)&C[i0] = make_float2((c[mt][nt][0] + bv.x + d0.x) * scale,
                                           (c[mt][nt][1] + bv.y + d0.y) * scale);
            *(float2*)&C[i1] = make_float2((c[mt][nt][2] + bv.x + d1.x) * scale,
                                           (c[mt][nt][3] + bv.y + d1.y) * scale);
        }
}

// ============================================================================
// converts
// ============================================================================
__global__ void convert_f16(const float4* __restrict__ src, __half2* __restrict__ h2)
{
    const int i = blockIdx.x * 256 + threadIdx.x;
    float4 v = src[i];
    h2[2*i]     = __floats2half2_rn(v.x, v.y);
    h2[2*i + 1] = __floats2half2_rn(v.z, v.w);
}

// transpose + convert: dst[c][r] = fp16(src[r][c]);  src [R,Cd]
__global__ void transpose_cvt(const float* __restrict__ src, __half* __restrict__ dst,
                              int R, int Cd)
{
    __shared__ float t[32][33];
    const int c0 = blockIdx.x * 32, r0 = blockIdx.y * 32;
    const int tx = threadIdx.x, ty = threadIdx.y;   // 32 x 8
    #pragma unroll
    for (int j = 0; j < 4; j++)
        t[ty + 8*j][tx] = src[(size_t)(r0 + ty + 8*j) * Cd + c0 + tx];
    __syncthreads();
    #pragma unroll
    for (int j = 0; j < 4; j++)
        dst[(size_t)(c0 + ty + 8*j) * R + r0 + tx] = __float2half_rn(t[tx][ty + 8*j]);
}

// ---------------- row softmax (in place) + fp16 copy ------------------------
__global__ void softmax_f16(float* __restrict__ attn, __half* __restrict__ af)
{
    const size_t row = blockIdx.x;
    float* p = attn + row * (size_t)Sc;
    __half* pf = af + row * (size_t)Sc;
    const int tid = threadIdx.x;   // 256 threads, 8 elems each
    __shared__ float red[256];
    float v[8];
    float mx = -CUDART_INF_F;
    #pragma unroll
    for (int i = 0; i < 8; i++) { v[i] = p[tid + i*256]; mx = fmaxf(mx, v[i]); }
    red[tid] = mx; __syncthreads();
    for (int s = 128; s > 0; s >>= 1) { if (tid < s) red[tid] = fmaxf(red[tid], red[tid+s]); __syncthreads(); }
    mx = red[0]; __syncthreads();
    float sum = 0.0f;
    #pragma unroll
    for (int i = 0; i < 8; i++) { v[i] = __expf(v[i] - mx); sum += v[i]; }
    red[tid] = sum; __syncthreads();
    for (int s = 128; s > 0; s >>= 1) { if (tid < s) red[tid] += red[tid+s]; __syncthreads(); }
    const float inv = 1.0f / red[0];
    #pragma unroll
    for (int i = 0; i < 8; i++) {
        float a = v[i] * inv;
        p[tid + i*256] = a;
        pf[tid + i*256] = __float2half_rn(a);
    }
}

// ---------------- x_mean[b][s] = mean_t attn[b][t][s] -----------------------
__global__ void xmean_k(const float* __restrict__ attn)
{
    const int b = blockIdx.y;
    const int s = blockIdx.x * 256 + threadIdx.x;
    const float* p = attn + (size_t)b * Tc * Sc + s;
    float sum = 0.0f;
    for (int t = 0; t < Tc; t++) sum += p[(size_t)t * Sc];
    g_xmean[b * Sc + s] = sum * (1.0f / Tc);
}

// ---------------- row inv-norms of strided enc_values + aa -----------------
__global__ void norm_aa_k(const float* __restrict__ V)
{
    const int b = blockIdx.x;
    const int w = threadIdx.x >> 5, lane = threadIdx.x & 31;
    for (int n = w; n < NSEL; n += 8) {
        const float* row = V + ((size_t)b * Sc + (size_t)n * STRIDEc) * Ec;
        float s = 0.0f;
        for (int e = lane; e < Ec; e += 32) { float x = row[e]; s = fmaf(x, x, s); }
        #pragma unroll
        for (int o = 16; o; o >>= 1) s += __shfl_down_sync(0xffffffffu, s, o);
        if (lane == 0) {
            g_invn[b * NSEL + n] = rsqrtf(s);
            g_aa[b * NSEL + n]   = g_xmean[b * Sc + n * STRIDEc];
        }
    }
}

// ---------------- L[b][n][m] = aa_n aa_m * <v_n,v_m>/(|v_n||v_m|) ----------
__global__ void L_k(const float* __restrict__ V)
{
    const int b = blockIdx.x, n = blockIdx.y;
    __shared__ float vn[Ec];
    const float* rn = V + ((size_t)b * Sc + (size_t)n * STRIDEc) * Ec;
    for (int e = threadIdx.x; e < Ec; e += 128) vn[e] = rn[e];
    __syncthreads();
    const int m = threadIdx.x;
    if (m < NSEL) {
        const float* rm = V + ((size_t)b * Sc + (size_t)m * STRIDEc) * Ec;
        float d = 0.0f;
        for (int e = 0; e < Ec; e++) d = fmaf(vn[e], rm[e], d);
        float val = d * g_invn[b*NSEL + n] * g_invn[b*NSEL + m]
                      * g_aa[b*NSEL + n]   * g_aa[b*NSEL + m];
        g_L[((size_t)b * NSEL + n) * NSEL + m] = val;
    }
}

// numpy-style argmax of logf(D[n]*mask[n]): first NaN wins; strict > keeps first max
__device__ __forceinline__ int argmax_logDm(const float* D, const float* msk)
{
    int J = 0; float best = -CUDART_INF_F; bool done = false;
    for (int n = 0; n < NSEL && !done; n++) {
        float v = logf(D[n] * msk[n]);
        if (isnan(v)) { J = n; done = true; }
        else if (v > best) { best = v; J = n; }
    }
    return J;
}

// ---------------- greedy bfgm selection (sequential, tiny) -----------------
__global__ void bfgm_k()
{
    const int b = blockIdx.x, tid = threadIdx.x;  // 128 threads
    __shared__ float Cm[NSEL][MS];
    __shared__ float D[NSEL], msk[NSEL], cjs[MS];
    __shared__ float djs;
    __shared__ int Jsh, sel[MS];
    const float* L = g_L + (size_t)b * NSEL * NSEL;

    if (tid < NSEL) {
        D[tid] = L[(size_t)tid * NSEL + tid];
        msk[tid] = 1.0f;
        #pragma unroll
        for (int k = 0; k < MS; k++) Cm[tid][k] = 0.0f;
    }
    __syncthreads();
    if (tid == 0) {
        int J = argmax_logDm(D, msk);
        Jsh = J; msk[J] = 0.0f; sel[0] = J;
    }
    __syncthreads();

    for (int t = 1; t < MS; t++) {
        const int J = Jsh;
        if (tid < MS) cjs[tid] = Cm[J][tid];
        if (tid == 0) djs = D[J];
        __syncthreads();
        if (tid < NSEL) {
            float Lj = L[(size_t)J * NSEL + tid];
            float cd = 0.0f;
            #pragma unroll
            for (int k = 0; k < MS; k++) cd = fmaf(Cm[tid][k], cjs[k], cd);
            float e = (Lj - cd) / djs * msk[tid];
            Cm[tid][t] = e;
            D[tid] -= e * e;
        }
        __syncthreads();
        if (tid == 0) {
            int Jn = argmax_logDm(D, msk);
            Jsh = Jn; msk[Jn] = 0.0f; sel[t] = Jn;
        }
        __syncthreads();
    }
    if (tid == 0) {
        for (int i = 1; i < MS; i++) {          // insertion sort ascending
            int key = sel[i], j = i - 1;
            while (j >= 0 && sel[j] > key) { sel[j+1] = sel[j]; j--; }
            sel[j+1] = key;
        }
        for (int k = 0; k < MS; k++) g_mu[b*MS + k] = sel[k];
    }
}

// ---------------- gaussian mixture -> softmax(dist) -> KL partial ----------
__global__ void distkl_k()
{
    const int b = blockIdx.x, tid = threadIdx.x;   // 256 threads, 8 s-values each
    __shared__ float red[256];
    int mus[MS];
    #pragma unroll
    for (int k = 0; k < MS; k++) mus[k] = g_mu[b*MS + k];

    float g[8];
    float mx = -CUDART_INF_F;
    #pragma unroll
    for (int i = 0; i < 8; i++) {
        const int s = tid + i*256;
        float acc = 0.0f;
        #pragma unroll
        for (int k = 0; k < MS; k++) {
            float z = (float)s - (float)mus[k];
            acc += expf(-z*z * (1.0f/18.0f));        // 2*sigma^2 = 18
        }
        acc *= 0.13298076013381091f;                 // 1/(sqrt(2pi)*3)
        g[i] = acc; mx = fmaxf(mx, acc);
    }
    red[tid] = mx; __syncthreads();
    for (int s = 128; s > 0; s >>= 1) { if (tid < s) red[tid] = fmaxf(red[tid], red[tid+s]); __syncthreads(); }
    mx = red[0]; __syncthreads();
    float sum = 0.0f;
    #pragma unroll
    for (int i = 0; i < 8; i++) { g[i] = expf(g[i] - mx); sum += g[i]; }
    red[tid] = sum; __syncthreads();
    for (int s = 128; s > 0; s >>= 1) { if (tid < s) red[tid] += red[tid+s]; __syncthreads(); }
    const float inv = 1.0f / red[0];
    __syncthreads();

    float kl = 0.0f;
    #pragma unroll
    for (int i = 0; i < 8; i++) {
        const int s = tid + i*256;
        float xm = g_xmean[b*Sc + s];
        kl += xm * (logf(xm) - g[i] * inv);
    }
    red[tid] = kl; __syncthreads();
    for (int s = 128; s > 0; s >>= 1) { if (tid < s) red[tid] += red[tid+s]; __syncthreads(); }
    if (tid == 0) atomicAdd(&g_kl, red[0]);
}

// ---------------- launch ----------------------------------------------------
extern "C" void kernel_launch(void* const* d_in, const int* in_sizes, int n_in,
                              void* d_out, int out_size)
{
    const float* x  = (const float*)d_in[0];
    const float* te = (const float*)d_in[1];
    const float* ek = (const float*)d_in[2];   // [B,E,S]
    const float* ev = (const float*)d_in[3];   // [B,S,E]
    const float* Wi = (const float*)d_in[4];   // [E,C]
    const float* bi = (const float*)d_in[5];
    const float* Wo = (const float*)d_in[6];   // [C,E]
    const float* bo = (const float*)d_in[7];

    float* out  = (float*)d_out;                              // [B,T,C]
    float* attn = out + (size_t)Bc * Tc * Cc;                 // [B,T,S]
    float* klp  = attn + (size_t)Bc * Tc * Sc;                // scalar

    __half *xf, *hf, *ekf, *evf, *af, *o1f, *WiT, *WoT;
    cudaGetSymbolAddress((void**)&xf,  g_xf);
    cudaGetSymbolAddress((void**)&hf,  g_hf);
    cudaGetSymbolAddress((void**)&ekf, g_ekf);
    cudaGetSymbolAddress((void**)&evf, g_evf);
    cudaGetSymbolAddress((void**)&af,  g_af);
    cudaGetSymbolAddress((void**)&o1f, g_o1f);
    cudaGetSymbolAddress((void**)&WiT, g_WiT);
    cudaGetSymbolAddress((void**)&WoT, g_WoT);

    cudaFuncSetAttribute(gemm_nn_fp16, cudaFuncAttributeMaxDynamicSharedMemorySize, NNF_SMEM);
    cudaFuncSetAttribute(gemm_nn_f16o, cudaFuncAttributeMaxDynamicSharedMemorySize, NNF_SMEM);
    cudaFuncSetAttribute(gemm_nn_epH,  cudaFuncAttributeMaxDynamicSharedMemorySize, NNF_SMEM);
    cudaFuncSetAttribute(gemm_nn_epF,  cudaFuncAttributeMaxDynamicSharedMemorySize, NNF_SMEM);

    const float SQ05 = 0.70710678118654752f;
    const float SQS  = 45.25483399593904f;    // s*sqrt(1/s), s=2048

    // converts / weight transposes
    const int nEK4 = Bc * Ec * Sc / 4;
    const int nX4  = Bc * Tc * Cc / 4;
    convert_f16<<<nEK4 / 256, 256>>>((const float4*)ek, (__half2*)ekf);
    convert_f16<<<nEK4 / 256, 256>>>((const float4*)ev, (__half2*)evf);
    convert_f16<<<nX4 / 256, 256>>>((const float4*)x, (__half2*)xf);
    transpose_cvt<<<dim3(Cc/32, Ec/32), dim3(32, 8)>>>(Wi, WiT, Ec, Cc);  // WiT [C,E]
    transpose_cvt<<<dim3(Ec/32, Cc/32), dim3(32, 8)>>>(Wo, WoT, Cc, Ec);  // WoT [E,C]

    // h = (x @ Wi^T + bi + te)*sqrt(.5)  -> fp16 (NN: xf[M,C] @ WiT[C,E])
    gemm_nn_epH<<<dim3(Ec/64, (Bc*Tc)/128, 1), 256, NNF_SMEM>>>(
        xf, WiT, bi, te, hf, Ec, Cc, SQ05);

    // scores = h @ enc_keys (fp16, fp32 out into attn region)
    gemm_nn_fp16<<<dim3(Sc/64, Tc/128, Bc), 256, NNF_SMEM>>>(
        hf, ekf, attn, Sc, Ec,
        (long long)Tc*Ec, (long long)Ec*Sc, (long long)Tc*Sc, 1.0f);

    // attn = softmax(scores) in place + fp16 copy
    softmax_f16<<<Bc*Tc, 256>>>(attn, af);

    // x_mean
    xmean_k<<<dim3(Sc/256, Bc), 256>>>(attn);

    // out1 = attn @ enc_values * sqrt(S)  -> fp16
    gemm_nn_f16o<<<dim3(Ec/64, Tc/128, Bc), 256, NNF_SMEM>>>(
        af, evf, o1f, Ec, Sc,
        (long long)Tc*Sc, (long long)Sc*Ec, (long long)Tc*Ec, SQS);

    // out = (out1 @ Wo^T + bo + x)*sqrt(.5)  (NN: o1f[M,E] @ WoT[E,C])
    gemm_nn_epF<<<dim3(Cc/64, (Bc*Tc)/128, 1), 256, NNF_SMEM>>>(
        o1f, WoT, bo, x, out, Cc, Ec, SQ05);

    // DPP side path
    init_k<<<1, 1>>>();
    norm_aa_k<<<Bc, 256>>>(ev);
    L_k<<<dim3(Bc, NSEL), 128>>>(ev);
    bfgm_k<<<Bc, 128>>>();
    distkl_k<<<Bc, 256>>>();
    final_k<<<1, 1>>>(klp);
}

// round 13
// speedup vs baseline: 1.7436x; 1.0717x over previous
#include <cuda_runtime.h>
#include <cuda_fp16.h>
#include <math_constants.h>
#include <math.h>
#include <stdint.h>

#define Bc 16
#define Tc 1024
#define Sc 2048
#define Cc 256
#define Ec 256
#define NSEL 103     // ceil(2048/20)
#define MS 20
#define STRIDEc 20
#define RPB 16       // rows per softmax block
#define NGRP (Tc/RPB) // 64 row groups per batch

// ---------------- scratch (device globals; no allocation allowed) ----------
__device__ __half g_xf[Bc*Tc*Cc];               // x fp16
__device__ __half g_hf[Bc*Tc*Ec];               // h fp16
__device__ __half g_ekf[Bc*Ec*Sc];              // enc_keys fp16
__device__ __half g_evf[Bc*Sc*Ec];              // enc_values fp16
__device__ __half g_af[(size_t)Bc*Tc*Sc];       // fp16 scores, then fp16 attn (in place)
__device__ __half g_o1f[Bc*Tc*Ec];              // out1 fp16
__device__ __half g_WiT[Cc*Ec];                 // Wi^T [C,E] fp16
__device__ __half g_WoT[Ec*Cc];                 // Wo^T [E,C] fp16
__device__ float g_part[(size_t)Bc*NGRP*Sc];    // xmean partials (8 MB)
__device__ float g_xmean[Bc*Sc];
__device__ float g_invn[Bc*NSEL];
__device__ float g_aa[Bc*NSEL];
__device__ float g_L[Bc*NSEL*NSEL];
__device__ int   g_mu[Bc*MS];
__device__ float g_kl;

// ---------------- small init / final ---------------------------------------
__global__ void init_k() { g_kl = 0.0f; }
__global__ void final_k(float* klout) { klout[0] = -g_kl; }

#define MMA_FP16(c, a, b) \
    asm volatile("mma.sync.aligned.m16n8k16.row.col.f32.f16.f16.f32 " \
        "{%0,%1,%2,%3}, {%4,%5,%6,%7}, {%8,%9}, {%0,%1,%2,%3};" \
        : "+f"((c)[0]), "+f"((c)[1]), "+f"((c)[2]), "+f"((c)[3]) \
        : "r"((a)[0]), "r"((a)[1]), "r"((a)[2]), "r"((a)[3]), \
          "r"((b)[0]), "r"((b)[1]))

#define LDSM4(r, addr) \
    asm volatile("ldmatrix.sync.aligned.m8n8.x4.shared.b16 {%0,%1,%2,%3}, [%4];" \
        : "=r"((r)[0]), "=r"((r)[1]), "=r"((r)[2]), "=r"((r)[3]) : "r"(addr))

#define LDSM4T(r, addr) \
    asm volatile("ldmatrix.sync.aligned.m8n8.x4.trans.shared.b16 {%0,%1,%2,%3}, [%4];" \
        : "=r"((r)[0]), "=r"((r)[1]), "=r"((r)[2]), "=r"((r)[3]) : "r"(addr))

__device__ __forceinline__ void cpa16s(uint32_t d, const void* gsrc)
{
    asm volatile("cp.async.cg.shared.global [%0], [%1], 16;" :: "r"(d), "l"(gsrc));
}
__device__ __forceinline__ void cpa_commit() { asm volatile("cp.async.commit_group;"); }
__device__ __forceinline__ void cpa_wait0()  { asm volatile("cp.async.wait_group 0;"); }
__device__ __forceinline__ void cpa_wait2()  { asm volatile("cp.async.wait_group 2;"); }

// ============================================================================
// Shared fp16 NN GEMM core: acc = A[M,K] @ B[K,N] block tile (BM=128 BN=64
// BK=32), 256 thr (8 warps 4x2), 6-stage cp.async, 1 barrier per k-pair.
// ============================================================================
#define NNF_A 0
#define NNF_B 10240
#define NNF_BUF 14848
#define NNF_STAGES 6
#define NNF_SMEM (NNF_STAGES*NNF_BUF)

__device__ __forceinline__ void nn_core(
    const __half* __restrict__ A, const __half* __restrict__ B,
    int N, int K, int m0, int n0, float c[2][4][4], char* smdyn)
{
    const int tid = threadIdx.x, lane = tid & 31, wid = tid >> 5;
    const int wm = (wid & 3) * 32, wn = (wid >> 2) * 32;
    const uint32_t sbase = (uint32_t)__cvta_generic_to_shared(smdyn);
    const int S = K / 32;

    auto issue = [&](int kt) {
        const uint32_t base = sbase + (kt % NNF_STAGES) * NNF_BUF;
        const int k0 = kt * 32;
        #pragma unroll
        for (int j = 0; j < 2; j++) {
            int ch = tid + j * 256, row = ch >> 2, cc = ch & 3;
            cpa16s(base + NNF_A + row * 80 + cc * 16, A + (size_t)(m0 + row) * K + k0 + cc * 8);
        }
        {
            int row = tid >> 3, cc = tid & 7;
            cpa16s(base + NNF_B + row * 144 + cc * 16, B + (size_t)(k0 + row) * N + n0 + cc * 8);
        }
        cpa_commit();
    };

    auto compute = [&](int s) {
        const uint32_t base = sbase + (s % NNF_STAGES) * NNF_BUF;
        #pragma unroll
        for (int ks = 0; ks < 2; ks++) {
            uint32_t a[2][4];
            #pragma unroll
            for (int mt = 0; mt < 2; mt++) {
                uint32_t addr = base + NNF_A
                    + (uint32_t)(wm + mt * 16 + (lane & 15)) * 80
                    + (uint32_t)(ks * 32 + (lane >> 4) * 16);
                LDSM4(a[mt], addr);
            }
            uint32_t b[2][4];
            #pragma unroll
            for (int bt = 0; bt < 2; bt++) {
                uint32_t addr = base + NNF_B
                    + (uint32_t)(ks * 16 + (lane & 15)) * 144
                    + (uint32_t)((wn + bt * 16) * 2 + (lane >> 4) * 16);
                LDSM4T(b[bt], addr);
            }
            #pragma unroll
            for (int mt = 0; mt < 2; mt++)
                #pragma unroll
                for (int nt = 0; nt < 4; nt++)
                    MMA_FP16(c[mt][nt], a[mt], (&b[nt >> 1][(nt & 1) * 2]));
        }
    };

    issue(0); issue(1); issue(2); issue(3);
    for (int s = 0; s < S; s += 2) {
        if (s + 2 < S) cpa_wait2(); else cpa_wait0();
        __syncthreads();
        if (s + 4 < S) issue(s + 4);
        if (s + 5 < S) issue(s + 5);
        compute(s);
        compute(s + 1);
    }
}

// ---- fp16-out batched GEMM: C = alpha * A@B ---------------------------------
__global__ __launch_bounds__(256, 2)
void gemm_nn_f16o(const __half* __restrict__ A, const __half* __restrict__ B,
                  __half* __restrict__ C, int N, int K,
                  long long sA, long long sB, long long sC, float alpha)
{
    extern __shared__ char smdyn[];
    const int bz = blockIdx.z;
    A += (size_t)bz * sA; B += (size_t)bz * sB; C += (size_t)bz * sC;
    const int m0 = blockIdx.y * 128, n0 = blockIdx.x * 64;
    const int lane = threadIdx.x & 31, wid = threadIdx.x >> 5;
    const int wm = (wid & 3) * 32, wn = (wid >> 2) * 32;
    const int g = lane >> 2, t = lane & 3;
    float c[2][4][4] = {};
    nn_core(A, B, N, K, m0, n0, c, smdyn);
    #pragma unroll
    for (int mt = 0; mt < 2; mt++)
        #pragma unroll
        for (int nt = 0; nt < 4; nt++) {
            int row = m0 + wm + mt * 16 + g;
            int col = n0 + wn + nt * 8 + 2 * t;
            *(__half2*)&C[(size_t)row * N + col] =
                __floats2half2_rn(alpha * c[mt][nt][0], alpha * c[mt][nt][1]);
            *(__half2*)&C[(size_t)(row + 8) * N + col] =
                __floats2half2_rn(alpha * c[mt][nt][2], alpha * c[mt][nt][3]);
        }
}

// ---- h: fp16 C = (A@B + bias + add)*scale -----------------------------------
__global__ __launch_bounds__(256, 2)
void gemm_nn_epH(const __half* __restrict__ A, const __half* __restrict__ B,
                 const float* __restrict__ bias, const float* __restrict__ add,
                 __half* __restrict__ C, int N, int K, float scale)
{
    extern __shared__ char smdyn[];
    const int m0 = blockIdx.y * 128, n0 = blockIdx.x * 64;
    const int lane = threadIdx.x & 31, wid = threadIdx.x >> 5;
    const int wm = (wid & 3) * 32, wn = (wid >> 2) * 32;
    const int g = lane >> 2, t = lane & 3;
    float c[2][4][4] = {};
    nn_core(A, B, N, K, m0, n0, c, smdyn);
    #pragma unroll
    for (int mt = 0; mt < 2; mt++)
        #pragma unroll
        for (int nt = 0; nt < 4; nt++) {
            int row = m0 + wm + mt * 16 + g;
            int col = n0 + wn + nt * 8 + 2 * t;
            float2 bv = *(const float2*)&bias[col];
            size_t i0 = (size_t)row * N + col;
            size_t i1 = (size_t)(row + 8) * N + col;
            float2 d0 = *(const float2*)&add[i0];
            float2 d1 = *(const float2*)&add[i1];
            *(__half2*)&C[i0] = __floats2half2_rn((c[mt][nt][0] + bv.x + d0.x) * scale,
                                                  (c[mt][nt][1] + bv.y + d0.y) * scale);
            *(__half2*)&C[i1] = __floats2half2_rn((c[mt][nt][2] + bv.x + d1.x) * scale,
                                                  (c[mt][nt][3] + bv.y + d1.y) * scale);
        }
}

// ---- final out: fp32 C = (A@B + bias + add)*scale ---------------------------
__global__ __launch_bounds__(256, 2)
void gemm_nn_epF(const __half* __restrict__ A, const __half* __restrict__ B,
                 const float* __restrict__ bias, const float* __restrict__ add,
                 float* __restrict__ C, int N, int K, float scale)
{
    extern __shared__ char smdyn[];
    const int m0 = blockIdx.y * 128, n0 = blockIdx.x * 64;
    const int lane = threadIdx.x & 31, wid = threadIdx.x >> 5;
    const int wm = (wid & 3) * 32, wn = (wid >> 2) * 32;
    const int g = lane >> 2, t = lane & 3;
    float c[2][4][4] = {};
    nn_core(A, B, N, K, m0, n0, c, smdyn);
    #pragma unroll
    for (int mt = 0; mt < 2; mt++)
        #pragma unroll
        for (int nt = 0; nt < 4; nt++) {
            int row = m0 + wm + mt * 16 + g;
            int col = n0 + wn + nt * 8 + 2 * t;
            float2 bv = *(const float2*)&bias[col];
            size_t i0 = (size_t)row * N + col;
            size_t i1 = (size_t)(row + 8) * N + col;
            float2 d0 = *(const float2*)&add[i0];
            float2 d1 = *(const float2*)&add[i1];
            *(float2*)&C[i0] = make_float2((c[mt][nt][0] + bv.x + d0.x) * scale,
                                           (c[mt][nt][1] + bv.y + d0.y) * scale);
            *(float2*)&C[i1] = make_float2((c[mt][nt][2] + bv.x + d1.x) * scale,
                                           (c[mt][nt][3] + bv.y + d1.y) * scale);
        }
}

// ============================================================================
// converts
// ============================================================================
__global__ void convert_f16(const float4* __restrict__ src, __half2* __restrict__ h2)
{
    const int i = blockIdx.x * 256 + threadIdx.x;
    float4 v = src[i];
    h2[2*i]     = __floats2half2_rn(v.x, v.y);
    h2[2*i + 1] = __floats2half2_rn(v.z, v.w);
}

// transpose + convert: dst[c][r] = fp16(src[r][c]);  src [R,Cd]
__global__ void transpose_cvt(const float* __restrict__ src, __half* __restrict__ dst,
                              int R, int Cd)
{
    __shared__ float t[32][33];
    const int c0 = blockIdx.x * 32, r0 = blockIdx.y * 32;
    const int tx = threadIdx.x, ty = threadIdx.y;   // 32 x 8
    #pragma unroll
    for (int j = 0; j < 4; j++)
        t[ty + 8*j][tx] = src[(size_t)(r0 + ty + 8*j) * Cd + c0 + tx];
    __syncthreads();
    #pragma unroll
    for (int j = 0; j < 4; j++)
        dst[(size_t)(c0 + ty + 8*j) * R + r0 + tx] = __float2half_rn(t[tx][ty + 8*j]);
}

// ============================================================================
// fused softmax: reads fp16 scores from af, writes fp32 attn (output) +
// fp16 attn in-place into af + per-block column partial sums for x_mean.
// RPB=16 rows per block, 256 threads (8 columns per thread).
// ============================================================================
__global__ void softmax_fused(__half* __restrict__ af, float* __restrict__ attn,
                              float* __restrict__ part)
{
    const int b = blockIdx.y, rg = blockIdx.x;
    const int tid = threadIdx.x;
    __shared__ float red[256];
    float acc[8] = {};

    for (int r = 0; r < RPB; r++) {
        const size_t row = (size_t)b * Tc + rg * RPB + r;
        __half* ps = af + row * Sc;
        float* pa = attn + row * Sc;
        float v[8];
        float mx = -CUDART_INF_F;
        #pragma unroll
        for (int i = 0; i < 8; i++) { v[i] = __half2float(ps[tid + i*256]); mx = fmaxf(mx, v[i]); }
        red[tid] = mx; __syncthreads();
        for (int s = 128; s > 0; s >>= 1) { if (tid < s) red[tid] = fmaxf(red[tid], red[tid+s]); __syncthreads(); }
        mx = red[0]; __syncthreads();
        float sum = 0.0f;
        #pragma unroll
        for (int i = 0; i < 8; i++) { v[i] = __expf(v[i] - mx); sum += v[i]; }
        red[tid] = sum; __syncthreads();
        for (int s = 128; s > 0; s >>= 1) { if (tid < s) red[tid] += red[tid+s]; __syncthreads(); }
        const float inv = 1.0f / red[0];
        __syncthreads();
        #pragma unroll
        for (int i = 0; i < 8; i++) {
            float a = v[i] * inv;
            pa[tid + i*256] = a;
            ps[tid + i*256] = __float2half_rn(a);
            acc[i] += a;
        }
    }
    float* pp = part + ((size_t)b * NGRP + rg) * Sc;
    #pragma unroll
    for (int i = 0; i < 8; i++) pp[tid + i*256] = acc[i];
}

__global__ void xmean_reduce(const float* __restrict__ part)
{
    const int b = blockIdx.y;
    const int s = blockIdx.x * 256 + threadIdx.x;
    const float* pp = part + (size_t)b * NGRP * Sc + s;
    float sum = 0.0f;
    #pragma unroll 8
    for (int g = 0; g < NGRP; g++) sum += pp[(size_t)g * Sc];
    g_xmean[b * Sc + s] = sum * (1.0f / Tc);
}

// ---------------- row inv-norms of strided enc_values + aa -----------------
__global__ void norm_aa_k(const float* __restrict__ V)
{
    const int b = blockIdx.x;
    const int w = threadIdx.x >> 5, lane = threadIdx.x & 31;
    for (int n = w; n < NSEL; n += 8) {
        const float* row = V + ((size_t)b * Sc + (size_t)n * STRIDEc) * Ec;
        float s = 0.0f;
        for (int e = lane; e < Ec; e += 32) { float x = row[e]; s = fmaf(x, x, s); }
        #pragma unroll
        for (int o = 16; o; o >>= 1) s += __shfl_down_sync(0xffffffffu, s, o);
        if (lane == 0) {
            g_invn[b * NSEL + n] = rsqrtf(s);
            g_aa[b * NSEL + n]   = g_xmean[b * Sc + n * STRIDEc];
        }
    }
}

// ---------------- L[b][n][m] = aa_n aa_m * <v_n,v_m>/(|v_n||v_m|) ----------
__global__ void L_k(const float* __restrict__ V)
{
    const int b = blockIdx.x, n = blockIdx.y;
    __shared__ float vn[Ec];
    const float* rn = V + ((size_t)b * Sc + (size_t)n * STRIDEc) * Ec;
    for (int e = threadIdx.x; e < Ec; e += 128) vn[e] = rn[e];
    __syncthreads();
    const int m = threadIdx.x;
    if (m < NSEL) {
        const float* rm = V + ((size_t)b * Sc + (size_t)m * STRIDEc) * Ec;
        float d = 0.0f;
        for (int e = 0; e < Ec; e++) d = fmaf(vn[e], rm[e], d);
        float val = d * g_invn[b*NSEL + n] * g_invn[b*NSEL + m]
                      * g_aa[b*NSEL + n]   * g_aa[b*NSEL + m];
        g_L[((size_t)b * NSEL + n) * NSEL + m] = val;
    }
}

// numpy-style argmax of logf(D[n]*mask[n]): first NaN wins; strict > keeps first max
__device__ __forceinline__ int argmax_logDm(const float* D, const float* msk)
{
    int J = 0; float best = -CUDART_INF_F; bool done = false;
    for (int n = 0; n < NSEL && !done; n++) {
        float v = logf(D[n] * msk[n]);
        if (isnan(v)) { J = n; done = true; }
        else if (v > best) { best = v; J = n; }
    }
    return J;
}

// ---------------- greedy bfgm selection (sequential, tiny) -----------------
__global__ void bfgm_k()
{
    const int b = blockIdx.x, tid = threadIdx.x;  // 128 threads
    __shared__ float Cm[NSEL][MS];
    __shared__ float D[NSEL], msk[NSEL], cjs[MS];
    __shared__ float djs;
    __shared__ int Jsh, sel[MS];
    const float* L = g_L + (size_t)b * NSEL * NSEL;

    if (tid < NSEL) {
        D[tid] = L[(size_t)tid * NSEL + tid];
        msk[tid] = 1.0f;
        #pragma unroll
        for (int k = 0; k < MS; k++) Cm[tid][k] = 0.0f;
    }
    __syncthreads();
    if (tid == 0) {
        int J = argmax_logDm(D, msk);
        Jsh = J; msk[J] = 0.0f; sel[0] = J;
    }
    __syncthreads();

    for (int t = 1; t < MS; t++) {
        const int J = Jsh;
        if (tid < MS) cjs[tid] = Cm[J][tid];
        if (tid == 0) djs = D[J];
        __syncthreads();
        if (tid < NSEL) {
            float Lj = L[(size_t)J * NSEL + tid];
            float cd = 0.0f;
            #pragma unroll
            for (int k = 0; k < MS; k++) cd = fmaf(Cm[tid][k], cjs[k], cd);
            float e = (Lj - cd) / djs * msk[tid];
            Cm[tid][t] = e;
            D[tid] -= e * e;
        }
        __syncthreads();
        if (tid == 0) {
            int Jn = argmax_logDm(D, msk);
            Jsh = Jn; msk[Jn] = 0.0f; sel[t] = Jn;
        }
        __syncthreads();
    }
    if (tid == 0) {
        for (int i = 1; i < MS; i++) {          // insertion sort ascending
            int key = sel[i], j = i - 1;
            while (j >= 0 && sel[j] > key) { sel[j+1] = sel[j]; j--; }
            sel[j+1] = key;
        }
        for (int k = 0; k < MS; k++) g_mu[b*MS + k] = sel[k];
    }
}

// ---------------- gaussian mixture -> softmax(dist) -> KL partial ----------
__global__ void distkl_k()
{
    const int b = blockIdx.x, tid = threadIdx.x;   // 256 threads, 8 s-values each
    __shared__ float red[256];
    int mus[MS];
    #pragma unroll
    for (int k = 0; k < MS; k++) mus[k] = g_mu[b*MS + k];

    float g[8];
    float mx = -CUDART_INF_F;
    #pragma unroll
    for (int i = 0; i < 8; i++) {
        const int s = tid + i*256;
        float acc = 0.0f;
        #pragma unroll
        for (int k = 0; k < MS; k++) {
            float z = (float)s - (float)mus[k];
            acc += expf(-z*z * (1.0f/18.0f));        // 2*sigma^2 = 18
        }
        acc *= 0.13298076013381091f;                 // 1/(sqrt(2pi)*3)
        g[i] = acc; mx = fmaxf(mx, acc);
    }
    red[tid] = mx; __syncthreads();
    for (int s = 128; s > 0; s >>= 1) { if (tid < s) red[tid] = fmaxf(red[tid], red[tid+s]); __syncthreads(); }
    mx = red[0]; __syncthreads();
    float sum = 0.0f;
    #pragma unroll
    for (int i = 0; i < 8; i++) { g[i] = expf(g[i] - mx); sum += g[i]; }
    red[tid] = sum; __syncthreads();
    for (int s = 128; s > 0; s >>= 1) { if (tid < s) red[tid] += red[tid+s]; __syncthreads(); }
    const float inv = 1.0f / red[0];
    __syncthreads();

    float kl = 0.0f;
    #pragma unroll
    for (int i = 0; i < 8; i++) {
        const int s = tid + i*256;
        float xm = g_xmean[b*Sc + s];
        kl += xm * (logf(xm) - g[i] * inv);
    }
    red[tid] = kl; __syncthreads();
    for (int s = 128; s > 0; s >>= 1) { if (tid < s) red[tid] += red[tid+s]; __syncthreads(); }
    if (tid == 0) atomicAdd(&g_kl, red[0]);
}

// ---------------- launch ----------------------------------------------------
extern "C" void kernel_launch(void* const* d_in, const int* in_sizes, int n_in,
                              void* d_out, int out_size)
{
    const float* x  = (const float*)d_in[0];
    const float* te = (const float*)d_in[1];
    const float* ek = (const float*)d_in[2];   // [B,E,S]
    const float* ev = (const float*)d_in[3];   // [B,S,E]
    const float* Wi = (const float*)d_in[4];   // [E,C]
    const float* bi = (const float*)d_in[5];
    const float* Wo = (const float*)d_in[6];   // [C,E]
    const float* bo = (const float*)d_in[7];

    float* out  = (float*)d_out;                              // [B,T,C]
    float* attn = out + (size_t)Bc * Tc * Cc;                 // [B,T,S]
    float* klp  = attn + (size_t)Bc * Tc * Sc;                // scalar

    __half *xf, *hf, *ekf, *evf, *af, *o1f, *WiT, *WoT;
    float* part;
    cudaGetSymbolAddress((void**)&xf,  g_xf);
    cudaGetSymbolAddress((void**)&hf,  g_hf);
    cudaGetSymbolAddress((void**)&ekf, g_ekf);
    cudaGetSymbolAddress((void**)&evf, g_evf);
    cudaGetSymbolAddress((void**)&af,  g_af);
    cudaGetSymbolAddress((void**)&o1f, g_o1f);
    cudaGetSymbolAddress((void**)&WiT, g_WiT);
    cudaGetSymbolAddress((void**)&WoT, g_WoT);
    cudaGetSymbolAddress((void**)&part, g_part);

    cudaFuncSetAttribute(gemm_nn_f16o, cudaFuncAttributeMaxDynamicSharedMemorySize, NNF_SMEM);
    cudaFuncSetAttribute(gemm_nn_epH,  cudaFuncAttributeMaxDynamicSharedMemorySize, NNF_SMEM);
    cudaFuncSetAttribute(gemm_nn_epF,  cudaFuncAttributeMaxDynamicSharedMemorySize, NNF_SMEM);

    const float SQ05 = 0.70710678118654752f;
    const float SQS  = 45.25483399593904f;    // s*sqrt(1/s), s=2048

    // converts / weight transposes
    const int nEK4 = Bc * Ec * Sc / 4;
    const int nX4  = Bc * Tc * Cc / 4;
    convert_f16<<<nEK4 / 256, 256>>>((const float4*)ek, (__half2*)ekf);
    convert_f16<<<nEK4 / 256, 256>>>((const float4*)ev, (__half2*)evf);
    convert_f16<<<nX4 / 256, 256>>>((const float4*)x, (__half2*)xf);
    transpose_cvt<<<dim3(Cc/32, Ec/32), dim3(32, 8)>>>(Wi, WiT, Ec, Cc);  // WiT [C,E]
    transpose_cvt<<<dim3(Ec/32, Cc/32), dim3(32, 8)>>>(Wo, WoT, Cc, Ec);  // WoT [E,C]

    // h = (x @ Wi^T + bi + te)*sqrt(.5)  -> fp16
    gemm_nn_epH<<<dim3(Ec/64, (Bc*Tc)/128, 1), 256, NNF_SMEM>>>(
        xf, WiT, bi, te, hf, Ec, Cc, SQ05);

    // scores = h @ enc_keys -> fp16 into g_af
    gemm_nn_f16o<<<dim3(Sc/64, Tc/128, Bc), 256, NNF_SMEM>>>(
        hf, ekf, af, Sc, Ec,
        (long long)Tc*Ec, (long long)Ec*Sc, (long long)Tc*Sc, 1.0f);

    // softmax (fp16 in, fp32 attn out + fp16 in-place) + xmean partials
    softmax_fused<<<dim3(NGRP, Bc), 256>>>(af, attn, part);
    xmean_reduce<<<dim3(Sc/256, Bc), 256>>>(part);

    // out1 = attn @ enc_values * sqrt(S)  -> fp16
    gemm_nn_f16o<<<dim3(Ec/64, Tc/128, Bc), 256, NNF_SMEM>>>(
        af, evf, o1f, Ec, Sc,
        (long long)Tc*Sc, (long long)Sc*Ec, (long long)Tc*Ec, SQS);

    // out = (out1 @ Wo^T + bo + x)*sqrt(.5)
    gemm_nn_epF<<<dim3(Cc/64, (Bc*Tc)/128, 1), 256, NNF_SMEM>>>(
        o1f, WoT, bo, x, out, Cc, Ec, SQ05);

    // DPP side path
    init_k<<<1, 1>>>();
    norm_aa_k<<<Bc, 256>>>(ev);
    L_k<<<dim3(Bc, NSEL), 128>>>(ev);
    bfgm_k<<<Bc, 128>>>();
    distkl_k<<<Bc, 256>>>();
    final_k<<<1, 1>>>(klp);
}

// round 14
// speedup vs baseline: 1.8493x; 1.0606x over previous
#include <cuda_runtime.h>
#include <cuda_fp16.h>
#include <math_constants.h>
#include <math.h>
#include <stdint.h>

#define Bc 16
#define Tc 1024
#define Sc 2048
#define Cc 256
#define Ec 256
#define NSEL 103     // ceil(2048/20)
#define MS 20
#define STRIDEc 20
#define RPB 16       // rows per softmax block
#define NGRP (Tc/RPB) // 64 row groups per batch

// ---------------- scratch (device globals; no allocation allowed) ----------
__device__ __half g_xf[Bc*Tc*Cc];               // x fp16
__device__ __half g_hf[Bc*Tc*Ec];               // h fp16
__device__ __half g_ekf[Bc*Ec*Sc];              // enc_keys fp16
__device__ __half g_evf[Bc*Sc*Ec];              // enc_values fp16
__device__ __half g_af[(size_t)Bc*Tc*Sc];       // fp16 scores, then fp16 attn (in place)
__device__ __half g_o1f[Bc*Tc*Ec];              // out1 fp16
__device__ __half g_WiT[Cc*Ec];                 // Wi^T [C,E] fp16
__device__ __half g_WoT[Ec*Cc];                 // Wo^T [E,C] fp16
__device__ float g_part[(size_t)Bc*NGRP*Sc];    // xmean partials (8 MB)
__device__ float g_xmean[Bc*Sc];
__device__ float g_invn[Bc*NSEL];
__device__ float g_aa[Bc*NSEL];
__device__ float g_L[Bc*NSEL*NSEL];
__device__ int   g_mu[Bc*MS];
__device__ float g_kl;

// ---------------- small init / final ---------------------------------------
__global__ void init_k() { g_kl = 0.0f; }
__global__ void final_k(float* klout) { klout[0] = -g_kl; }

#define MMA_FP16(c, a, b) \
    asm volatile("mma.sync.aligned.m16n8k16.row.col.f32.f16.f16.f32 " \
        "{%0,%1,%2,%3}, {%4,%5,%6,%7}, {%8,%9}, {%0,%1,%2,%3};" \
        : "+f"((c)[0]), "+f"((c)[1]), "+f"((c)[2]), "+f"((c)[3]) \
        : "r"((a)[0]), "r"((a)[1]), "r"((a)[2]), "r"((a)[3]), \
          "r"((b)[0]), "r"((b)[1]))

#define LDSM4(r, addr) \
    asm volatile("ldmatrix.sync.aligned.m8n8.x4.shared.b16 {%0,%1,%2,%3}, [%4];" \
        : "=r"((r)[0]), "=r"((r)[1]), "=r"((r)[2]), "=r"((r)[3]) : "r"(addr))

#define LDSM4T(r, addr) \
    asm volatile("ldmatrix.sync.aligned.m8n8.x4.trans.shared.b16 {%0,%1,%2,%3}, [%4];" \
        : "=r"((r)[0]), "=r"((r)[1]), "=r"((r)[2]), "=r"((r)[3]) : "r"(addr))

__device__ __forceinline__ void cpa16s(uint32_t d, const void* gsrc)
{
    asm volatile("cp.async.cg.shared.global [%0], [%1], 16;" :: "r"(d), "l"(gsrc));
}
__device__ __forceinline__ void cpa_commit() { asm volatile("cp.async.commit_group;"); }
__device__ __forceinline__ void cpa_wait0()  { asm volatile("cp.async.wait_group 0;"); }
__device__ __forceinline__ void cpa_wait2()  { asm volatile("cp.async.wait_group 2;"); }

// ============================================================================
// 128x64 fp16 NN core (proven; used for weight GEMMs): BK=32, 8 warps 4x2,
// warp tile 32x32, 6-stage cp.async, 1 barrier per k-pair.
// ============================================================================
#define NNF_A 0
#define NNF_B 10240
#define NNF_BUF 14848
#define NNF_STAGES 6
#define NNF_SMEM (NNF_STAGES*NNF_BUF)

__device__ __forceinline__ void nn_core(
    const __half* __restrict__ A, const __half* __restrict__ B,
    int N, int K, int m0, int n0, float c[2][4][4], char* smdyn)
{
    const int tid = threadIdx.x, lane = tid & 31, wid = tid >> 5;
    const int wm = (wid & 3) * 32, wn = (wid >> 2) * 32;
    const uint32_t sbase = (uint32_t)__cvta_generic_to_shared(smdyn);
    const int S = K / 32;

    auto issue = [&](int kt) {
        const uint32_t base = sbase + (kt % NNF_STAGES) * NNF_BUF;
        const int k0 = kt * 32;
        #pragma unroll
        for (int j = 0; j < 2; j++) {
            int ch = tid + j * 256, row = ch >> 2, cc = ch & 3;
            cpa16s(base + NNF_A + row * 80 + cc * 16, A + (size_t)(m0 + row) * K + k0 + cc * 8);
        }
        {
            int row = tid >> 3, cc = tid & 7;
            cpa16s(base + NNF_B + row * 144 + cc * 16, B + (size_t)(k0 + row) * N + n0 + cc * 8);
        }
        cpa_commit();
    };

    auto compute = [&](int s) {
        const uint32_t base = sbase + (s % NNF_STAGES) * NNF_BUF;
        #pragma unroll
        for (int ks = 0; ks < 2; ks++) {
            uint32_t a[2][4];
            #pragma unroll
            for (int mt = 0; mt < 2; mt++) {
                uint32_t addr = base + NNF_A
                    + (uint32_t)(wm + mt * 16 + (lane & 15)) * 80
                    + (uint32_t)(ks * 32 + (lane >> 4) * 16);
                LDSM4(a[mt], addr);
            }
            uint32_t b[2][4];
            #pragma unroll
            for (int bt = 0; bt < 2; bt++) {
                uint32_t addr = base + NNF_B
                    + (uint32_t)(ks * 16 + (lane & 15)) * 144
                    + (uint32_t)((wn + bt * 16) * 2 + (lane >> 4) * 16);
                LDSM4T(b[bt], addr);
            }
            #pragma unroll
            for (int mt = 0; mt < 2; mt++)
                #pragma unroll
                for (int nt = 0; nt < 4; nt++)
                    MMA_FP16(c[mt][nt], a[mt], (&b[nt >> 1][(nt & 1) * 2]));
        }
    };

    issue(0); issue(1); issue(2); issue(3);
    for (int s = 0; s < S; s += 2) {
        if (s + 2 < S) cpa_wait2(); else cpa_wait0();
        __syncthreads();
        if (s + 4 < S) issue(s + 4);
        if (s + 5 < S) issue(s + 5);
        compute(s);
        compute(s + 1);
    }
}

// ============================================================================
// 128x128 fp16 NN GEMM (big batched GEMMs): warp tile 32x64, fp16 out.
// smem/stage: A 128x(32h,80B stride)=10240, B 32x(128h,272B stride)=8704.
// ============================================================================
#define BIG_A 0
#define BIG_B 10240
#define BIG_BUF 18944
#define BIG_STAGES 6
#define BIG_SMEM (BIG_STAGES*BIG_BUF)

__global__ __launch_bounds__(256, 2)
void gemm_big_f16(const __half* __restrict__ A, const __half* __restrict__ B,
                  __half* __restrict__ C, int N, int K,
                  long long sA, long long sB, long long sC, float alpha)
{
    extern __shared__ char smdyn[];
    const int bz = blockIdx.z;
    A += (size_t)bz * sA; B += (size_t)bz * sB; C += (size_t)bz * sC;
    const int m0 = blockIdx.y * 128, n0 = blockIdx.x * 128;
    const int tid = threadIdx.x, lane = tid & 31, wid = tid >> 5;
    const int wm = (wid & 3) * 32, wn = (wid >> 2) * 64;
    const int g = lane >> 2, t = lane & 3;
    const uint32_t sbase = (uint32_t)__cvta_generic_to_shared(smdyn);
    const int S = K / 32;

    float c[2][8][4] = {};

    auto issue = [&](int kt) {
        const uint32_t base = sbase + (kt % BIG_STAGES) * BIG_BUF;
        const int k0 = kt * 32;
        #pragma unroll
        for (int j = 0; j < 2; j++) {
            int ch = tid + j * 256, row = ch >> 2, cc = ch & 3;
            cpa16s(base + BIG_A + row * 80 + cc * 16, A + (size_t)(m0 + row) * K + k0 + cc * 8);
        }
        #pragma unroll
        for (int j = 0; j < 2; j++) {
            int ch = tid + j * 256, row = ch >> 4, cc = ch & 15;
            cpa16s(base + BIG_B + row * 272 + cc * 16, B + (size_t)(k0 + row) * N + n0 + cc * 8);
        }
        cpa_commit();
    };

    auto compute = [&](int s) {
        const uint32_t base = sbase + (s % BIG_STAGES) * BIG_BUF;
        #pragma unroll
        for (int ks = 0; ks < 2; ks++) {
            uint32_t a[2][4];
            #pragma unroll
            for (int mt = 0; mt < 2; mt++) {
                uint32_t addr = base + BIG_A
                    + (uint32_t)(wm + mt * 16 + (lane & 15)) * 80
                    + (uint32_t)(ks * 32 + (lane >> 4) * 16);
                LDSM4(a[mt], addr);
            }
            uint32_t b[4][4];
            #pragma unroll
            for (int bt = 0; bt < 4; bt++) {
                uint32_t addr = base + BIG_B
                    + (uint32_t)(ks * 16 + (lane & 15)) * 272
                    + (uint32_t)((wn + bt * 16) * 2 + (lane >> 4) * 16);
                LDSM4T(b[bt], addr);
            }
            #pragma unroll
            for (int mt = 0; mt < 2; mt++)
                #pragma unroll
                for (int nt = 0; nt < 8; nt++)
                    MMA_FP16(c[mt][nt], a[mt], (&b[nt >> 1][(nt & 1) * 2]));
        }
    };

    issue(0); issue(1); issue(2); issue(3);
    for (int s = 0; s < S; s += 2) {
        if (s + 2 < S) cpa_wait2(); else cpa_wait0();
        __syncthreads();
        if (s + 4 < S) issue(s + 4);
        if (s + 5 < S) issue(s + 5);
        compute(s);
        compute(s + 1);
    }

    #pragma unroll
    for (int mt = 0; mt < 2; mt++)
        #pragma unroll
        for (int nt = 0; nt < 8; nt++) {
            int row = m0 + wm + mt * 16 + g;
            int col = n0 + wn + nt * 8 + 2 * t;
            *(__half2*)&C[(size_t)row * N + col] =
                __floats2half2_rn(alpha * c[mt][nt][0], alpha * c[mt][nt][1]);
            *(__half2*)&C[(size_t)(row + 8) * N + col] =
                __floats2half2_rn(alpha * c[mt][nt][2], alpha * c[mt][nt][3]);
        }
}

// ---- h: fp16 C = (A@B + bias + add)*scale -----------------------------------
__global__ __launch_bounds__(256, 2)
void gemm_nn_epH(const __half* __restrict__ A, const __half* __restrict__ B,
                 const float* __restrict__ bias, const float* __restrict__ add,
                 __half* __restrict__ C, int N, int K, float scale)
{
    extern __shared__ char smdyn[];
    const int m0 = blockIdx.y * 128, n0 = blockIdx.x * 64;
    const int lane = threadIdx.x & 31, wid = threadIdx.x >> 5;
    const int wm = (wid & 3) * 32, wn = (wid >> 2) * 32;
    const int g = lane >> 2, t = lane & 3;
    float c[2][4][4] = {};
    nn_core(A, B, N, K, m0, n0, c, smdyn);
    #pragma unroll
    for (int mt = 0; mt < 2; mt++)
        #pragma unroll
        for (int nt = 0; nt < 4; nt++) {
            int row = m0 + wm + mt * 16 + g;
            int col = n0 + wn + nt * 8 + 2 * t;
            float2 bv = *(const float2*)&bias[col];
            size_t i0 = (size_t)row * N + col;
            size_t i1 = (size_t)(row + 8) * N + col;
            float2 d0 = *(const float2*)&add[i0];
            float2 d1 = *(const float2*)&add[i1];
            *(__half2*)&C[i0] = __floats2half2_rn((c[mt][nt][0] + bv.x + d0.x) * scale,
                                                  (c[mt][nt][1] + bv.y + d0.y) * scale);
            *(__half2*)&C[i1] = __floats2half2_rn((c[mt][nt][2] + bv.x + d1.x) * scale,
                                                  (c[mt][nt][3] + bv.y + d1.y) * scale);
        }
}

// ---- final out: fp32 C = (A@B + bias + add)*scale ---------------------------
__global__ __launch_bounds__(256, 2)
void gemm_nn_epF(const __half* __restrict__ A, const __half* __restrict__ B,
                 const float* __restrict__ bias, const float* __restrict__ add,
                 float* __restrict__ C, int N, int K, float scale)
{
    extern __shared__ char smdyn[];
    const int m0 = blockIdx.y * 128, n0 = blockIdx.x * 64;
    const int lane = threadIdx.x & 31, wid = threadIdx.x >> 5;
    const int wm = (wid & 3) * 32, wn = (wid >> 2) * 32;
    const int g = lane >> 2, t = lane & 3;
    float c[2][4][4] = {};
    nn_core(A, B, N, K, m0, n0, c, smdyn);
    #pragma unroll
    for (int mt = 0; mt < 2; mt++)
        #pragma unroll
        for (int nt = 0; nt < 4; nt++) {
            int row = m0 + wm + mt * 16 + g;
            int col = n0 + wn + nt * 8 + 2 * t;
            float2 bv = *(const float2*)&bias[col];
            size_t i0 = (size_t)row * N + col;
            size_t i1 = (size_t)(row + 8) * N + col;
            float2 d0 = *(const float2*)&add[i0];
            float2 d1 = *(const float2*)&add[i1];
            *(float2*)&C[i0] = make_float2((c[mt][nt][0] + bv.x + d0.x) * scale,
                                           (c[mt][nt][1] + bv.y + d0.y) * scale);
            *(float2*)&C[i1] = make_float2((c[mt][nt][2] + bv.x + d1.x) * scale,
                                           (c[mt][nt][3] + bv.y + d1.y) * scale);
        }
}

// ============================================================================
// converts
// ============================================================================
__global__ void convert_f16(const float4* __restrict__ src, __half2* __restrict__ h2)
{
    const int i = blockIdx.x * 256 + threadIdx.x;
    float4 v = src[i];
    h2[2*i]     = __floats2half2_rn(v.x, v.y);
    h2[2*i + 1] = __floats2half2_rn(v.z, v.w);
}

// transpose + convert: dst[c][r] = fp16(src[r][c]);  src [R,Cd]
__global__ void transpose_cvt(const float* __restrict__ src, __half* __restrict__ dst,
                              int R, int Cd)
{
    __shared__ float t[32][33];
    const int c0 = blockIdx.x * 32, r0 = blockIdx.y * 32;
    const int tx = threadIdx.x, ty = threadIdx.y;   // 32 x 8
    #pragma unroll
    for (int j = 0; j < 4; j++)
        t[ty + 8*j][tx] = src[(size_t)(r0 + ty + 8*j) * Cd + c0 + tx];
    __syncthreads();
    #pragma unroll
    for (int j = 0; j < 4; j++)
        dst[(size_t)(c0 + ty + 8*j) * R + r0 + tx] = __float2half_rn(t[tx][ty + 8*j]);
}

// ============================================================================
// fused softmax: reads fp16 scores from af, writes fp32 attn (output) +
// fp16 attn in-place into af + per-block column partial sums for x_mean.
// ============================================================================
__global__ void softmax_fused(__half* __restrict__ af, float* __restrict__ attn,
                              float* __restrict__ part)
{
    const int b = blockIdx.y, rg = blockIdx.x;
    const int tid = threadIdx.x;
    __shared__ float red[256];
    float acc[8] = {};

    for (int r = 0; r < RPB; r++) {
        const size_t row = (size_t)b * Tc + rg * RPB + r;
        __half* ps = af + row * Sc;
        float* pa = attn + row * Sc;
        float v[8];
        float mx = -CUDART_INF_F;
        #pragma unroll
        for (int i = 0; i < 8; i++) { v[i] = __half2float(ps[tid + i*256]); mx = fmaxf(mx, v[i]); }
        red[tid] = mx; __syncthreads();
        for (int s = 128; s > 0; s >>= 1) { if (tid < s) red[tid] = fmaxf(red[tid], red[tid+s]); __syncthreads(); }
        mx = red[0]; __syncthreads();
        float sum = 0.0f;
        #pragma unroll
        for (int i = 0; i < 8; i++) { v[i] = __expf(v[i] - mx); sum += v[i]; }
        red[tid] = sum; __syncthreads();
        for (int s = 128; s > 0; s >>= 1) { if (tid < s) red[tid] += red[tid+s]; __syncthreads(); }
        const float inv = 1.0f / red[0];
        __syncthreads();
        #pragma unroll
        for (int i = 0; i < 8; i++) {
            float a = v[i] * inv;
            pa[tid + i*256] = a;
            ps[tid + i*256] = __float2half_rn(a);
            acc[i] += a;
        }
    }
    float* pp = part + ((size_t)b * NGRP + rg) * Sc;
    #pragma unroll
    for (int i = 0; i < 8; i++) pp[tid + i*256] = acc[i];
}

__global__ void xmean_reduce(const float* __restrict__ part)
{
    const int b = blockIdx.y;
    const int s = blockIdx.x * 256 + threadIdx.x;
    const float* pp = part + (size_t)b * NGRP * Sc + s;
    float sum = 0.0f;
    #pragma unroll 8
    for (int g = 0; g < NGRP; g++) sum += pp[(size_t)g * Sc];
    g_xmean[b * Sc + s] = sum * (1.0f / Tc);
}

// ---------------- row inv-norms of strided enc_values + aa -----------------
__global__ void norm_aa_k(const float* __restrict__ V)
{
    const int b = blockIdx.x;
    const int w = threadIdx.x >> 5, lane = threadIdx.x & 31;
    for (int n = w; n < NSEL; n += 8) {
        const float* row = V + ((size_t)b * Sc + (size_t)n * STRIDEc) * Ec;
        float s = 0.0f;
        for (int e = lane; e < Ec; e += 32) { float x = row[e]; s = fmaf(x, x, s); }
        #pragma unroll
        for (int o = 16; o; o >>= 1) s += __shfl_down_sync(0xffffffffu, s, o);
        if (lane == 0) {
            g_invn[b * NSEL + n] = rsqrtf(s);
            g_aa[b * NSEL + n]   = g_xmean[b * Sc + n * STRIDEc];
        }
    }
}

// ---------------- L[b][n][m] = aa_n aa_m * <v_n,v_m>/(|v_n||v_m|) ----------
__global__ void L_k(const float* __restrict__ V)
{
    const int b = blockIdx.x, n = blockIdx.y;
    __shared__ float vn[Ec];
    const float* rn = V + ((size_t)b * Sc + (size_t)n * STRIDEc) * Ec;
    for (int e = threadIdx.x; e < Ec; e += 128) vn[e] = rn[e];
    __syncthreads();
    const int m = threadIdx.x;
    if (m < NSEL) {
        const float* rm = V + ((size_t)b * Sc + (size_t)m * STRIDEc) * Ec;
        float d = 0.0f;
        for (int e = 0; e < Ec; e++) d = fmaf(vn[e], rm[e], d);
        float val = d * g_invn[b*NSEL + n] * g_invn[b*NSEL + m]
                      * g_aa[b*NSEL + n]   * g_aa[b*NSEL + m];
        g_L[((size_t)b * NSEL + n) * NSEL + m] = val;
    }
}

// numpy-style argmax of logf(D[n]*mask[n]): first NaN wins; strict > keeps first max
__device__ __forceinline__ int argmax_logDm(const float* D, const float* msk)
{
    int J = 0; float best = -CUDART_INF_F; bool done = false;
    for (int n = 0; n < NSEL && !done; n++) {
        float v = logf(D[n] * msk[n]);
        if (isnan(v)) { J = n; done = true; }
        else if (v > best) { best = v; J = n; }
    }
    return J;
}

// ---------------- greedy bfgm selection (sequential, tiny) -----------------
__global__ void bfgm_k()
{
    const int b = blockIdx.x, tid = threadIdx.x;  // 128 threads
    __shared__ float Cm[NSEL][MS];
    __shared__ float D[NSEL], msk[NSEL], cjs[MS];
    __shared__ float djs;
    __shared__ int Jsh, sel[MS];
    const float* L = g_L + (size_t)b * NSEL * NSEL;

    if (tid < NSEL) {
        D[tid] = L[(size_t)tid * NSEL + tid];
        msk[tid] = 1.0f;
        #pragma unroll
        for (int k = 0; k < MS; k++) Cm[tid][k] = 0.0f;
    }
    __syncthreads();
    if (tid == 0) {
        int J = argmax_logDm(D, msk);
        Jsh = J; msk[J] = 0.0f; sel[0] = J;
    }
    __syncthreads();

    for (int t = 1; t < MS; t++) {
        const int J = Jsh;
        if (tid < MS) cjs[tid] = Cm[J][tid];
        if (tid == 0) djs = D[J];
        __syncthreads();
        if (tid < NSEL) {
            float Lj = L[(size_t)J * NSEL + tid];
            float cd = 0.0f;
            #pragma unroll
            for (int k = 0; k < MS; k++) cd = fmaf(Cm[tid][k], cjs[k], cd);
            float e = (Lj - cd) / djs * msk[tid];
            Cm[tid][t] = e;
            D[tid] -= e * e;
        }
        __syncthreads();
        if (tid == 0) {
            int Jn = argmax_logDm(D, msk);
            Jsh = Jn; msk[Jn] = 0.0f; sel[t] = Jn;
        }
        __syncthreads();
    }
    if (tid == 0) {
        for (int i = 1; i < MS; i++) {          // insertion sort ascending
            int key = sel[i], j = i - 1;
            while (j >= 0 && sel[j] > key) { sel[j+1] = sel[j]; j--; }
            sel[j+1] = key;
        }
        for (int k = 0; k < MS; k++) g_mu[b*MS + k] = sel[k];
    }
}

// ---------------- gaussian mixture -> softmax(dist) -> KL partial ----------
__global__ void distkl_k()
{
    const int b = blockIdx.x, tid = threadIdx.x;   // 256 threads, 8 s-values each
    __shared__ float red[256];
    int mus[MS];
    #pragma unroll
    for (int k = 0; k < MS; k++) mus[k] = g_mu[b*MS + k];

    float g[8];
    float mx = -CUDART_INF_F;
    #pragma unroll
    for (int i = 0; i < 8; i++) {
        const int s = tid + i*256;
        float acc = 0.0f;
        #pragma unroll
        for (int k = 0; k < MS; k++) {
            float z = (float)s - (float)mus[k];
            acc += expf(-z*z * (1.0f/18.0f));        // 2*sigma^2 = 18
        }
        acc *= 0.13298076013381091f;                 // 1/(sqrt(2pi)*3)
        g[i] = acc; mx = fmaxf(mx, acc);
    }
    red[tid] = mx; __syncthreads();
    for (int s = 128; s > 0; s >>= 1) { if (tid < s) red[tid] = fmaxf(red[tid], red[tid+s]); __syncthreads(); }
    mx = red[0]; __syncthreads();
    float sum = 0.0f;
    #pragma unroll
    for (int i = 0; i < 8; i++) { g[i] = expf(g[i] - mx); sum += g[i]; }
    red[tid] = sum; __syncthreads();
    for (int s = 128; s > 0; s >>= 1) { if (tid < s) red[tid] += red[tid+s]; __syncthreads(); }
    const float inv = 1.0f / red[0];
    __syncthreads();

    float kl = 0.0f;
    #pragma unroll
    for (int i = 0; i < 8; i++) {
        const int s = tid + i*256;
        float xm = g_xmean[b*Sc + s];
        kl += xm * (logf(xm) - g[i] * inv);
    }
    red[tid] = kl; __syncthreads();
    for (int s = 128; s > 0; s >>= 1) { if (tid < s) red[tid] += red[tid+s]; __syncthreads(); }
    if (tid == 0) atomicAdd(&g_kl, red[0]);
}

// ---------------- launch ----------------------------------------------------
extern "C" void kernel_launch(void* const* d_in, const int* in_sizes, int n_in,
                              void* d_out, int out_size)
{
    const float* x  = (const float*)d_in[0];
    const float* te = (const float*)d_in[1];
    const float* ek = (const float*)d_in[2];   // [B,E,S]
    const float* ev = (const float*)d_in[3];   // [B,S,E]
    const float* Wi = (const float*)d_in[4];   // [E,C]
    const float* bi = (const float*)d_in[5];
    const float* Wo = (const float*)d_in[6];   // [C,E]
    const float* bo = (const float*)d_in[7];

    float* out  = (float*)d_out;                              // [B,T,C]
    float* attn = out + (size_t)Bc * Tc * Cc;                 // [B,T,S]
    float* klp  = attn + (size_t)Bc * Tc * Sc;                // scalar

    __half *xf, *hf, *ekf, *evf, *af, *o1f, *WiT, *WoT;
    float* part;
    cudaGetSymbolAddress((void**)&xf,  g_xf);
    cudaGetSymbolAddress((void**)&hf,  g_hf);
    cudaGetSymbolAddress((void**)&ekf, g_ekf);
    cudaGetSymbolAddress((void**)&evf, g_evf);
    cudaGetSymbolAddress((void**)&af,  g_af);
    cudaGetSymbolAddress((void**)&o1f, g_o1f);
    cudaGetSymbolAddress((void**)&WiT, g_WiT);
    cudaGetSymbolAddress((void**)&WoT, g_WoT);
    cudaGetSymbolAddress((void**)&part, g_part);

    cudaFuncSetAttribute(gemm_big_f16, cudaFuncAttributeMaxDynamicSharedMemorySize, BIG_SMEM);
    cudaFuncSetAttribute(gemm_nn_epH,  cudaFuncAttributeMaxDynamicSharedMemorySize, NNF_SMEM);
    cudaFuncSetAttribute(gemm_nn_epF,  cudaFuncAttributeMaxDynamicSharedMemorySize, NNF_SMEM);

    const float SQ05 = 0.70710678118654752f;
    const float SQS  = 45.25483399593904f;    // s*sqrt(1/s), s=2048

    // converts / weight transposes
    const int nEK4 = Bc * Ec * Sc / 4;
    const int nX4  = Bc * Tc * Cc / 4;
    convert_f16<<<nEK4 / 256, 256>>>((const float4*)ek, (__half2*)ekf);
    convert_f16<<<nEK4 / 256, 256>>>((const float4*)ev, (__half2*)evf);
    convert_f16<<<nX4 / 256, 256>>>((const float4*)x, (__half2*)xf);
    transpose_cvt<<<dim3(Cc/32, Ec/32), dim3(32, 8)>>>(Wi, WiT, Ec, Cc);  // WiT [C,E]
    transpose_cvt<<<dim3(Ec/32, Cc/32), dim3(32, 8)>>>(Wo, WoT, Cc, Ec);  // WoT [E,C]

    // h = (x @ Wi^T + bi + te)*sqrt(.5)  -> fp16
    gemm_nn_epH<<<dim3(Ec/64, (Bc*Tc)/128, 1), 256, NNF_SMEM>>>(
        xf, WiT, bi, te, hf, Ec, Cc, SQ05);

    // scores = h @ enc_keys -> fp16 into g_af (128x128 tile)
    gemm_big_f16<<<dim3(Sc/128, Tc/128, Bc), 256, BIG_SMEM>>>(
        hf, ekf, af, Sc, Ec,
        (long long)Tc*Ec, (long long)Ec*Sc, (long long)Tc*Sc, 1.0f);

    // softmax (fp16 in, fp32 attn out + fp16 in-place) + xmean partials
    softmax_fused<<<dim3(NGRP, Bc), 256>>>(af, attn, part);
    xmean_reduce<<<dim3(Sc/256, Bc), 256>>>(part);

    // out1 = attn @ enc_values * sqrt(S)  -> fp16 (128x128 tile)
    gemm_big_f16<<<dim3(Ec/128, Tc/128, Bc), 256, BIG_SMEM>>>(
        af, evf, o1f, Ec, Sc,
        (long long)Tc*Sc, (long long)Sc*Ec, (long long)Tc*Ec, SQS);

    // out = (out1 @ Wo^T + bo + x)*sqrt(.5)
    gemm_nn_epF<<<dim3(Cc/64, (Bc*Tc)/128, 1), 256, NNF_SMEM>>>(
        o1f, WoT, bo, x, out, Cc, Ec, SQ05);

    // DPP side path
    init_k<<<1, 1>>>();
    norm_aa_k<<<Bc, 256>>>(ev);
    L_k<<<dim3(Bc, NSEL), 128>>>(ev);
    bfgm_k<<<Bc, 128>>>();
    distkl_k<<<Bc, 256>>>();
    final_k<<<1, 1>>>(klp);
}

// round 15
// speedup vs baseline: 1.8743x; 1.0135x over previous
#include <cuda_runtime.h>
#include <cuda_fp16.h>
#include <math_constants.h>
#include <math.h>
#include <stdint.h>

#define Bc 16
#define Tc 1024
#define Sc 2048
#define Cc 256
#define Ec 256
#define NSEL 103     // ceil(2048/20)
#define MS 20
#define STRIDEc 20
#define RPB 16       // rows per softmax block
#define NGRP (Tc/RPB) // 64 row groups per batch

// ---------------- scratch (device globals; no allocation allowed) ----------
__device__ __half g_xf[Bc*Tc*Cc];               // x fp16
__device__ __half g_hf[Bc*Tc*Ec];               // h fp16
__device__ __half g_ekf[Bc*Ec*Sc];              // enc_keys fp16
__device__ __half g_evf[Bc*Sc*Ec];              // enc_values fp16
__device__ __half g_af[(size_t)Bc*Tc*Sc];       // fp16 scores, then fp16 attn (in place)
__device__ __half g_o1f[Bc*Tc*Ec];              // out1 fp16
__device__ __half g_WiT[Cc*Ec];                 // Wi^T [C,E] fp16
__device__ __half g_WoT[Ec*Cc];                 // Wo^T [E,C] fp16
__device__ float g_part[(size_t)Bc*NGRP*Sc];    // xmean partials (8 MB)
__device__ float g_xmean[Bc*Sc];
__device__ float g_invn[Bc*NSEL];
__device__ float g_aa[Bc*NSEL];
__device__ float g_L[Bc*NSEL*NSEL];
__device__ int   g_mu[Bc*MS];
__device__ float g_kl;

// ---------------- small init / final ---------------------------------------
__global__ void init_k() { g_kl = 0.0f; }
__global__ void final_k(float* klout) { klout[0] = -g_kl; }

#define MMA_FP16(c, a, b) \
    asm volatile("mma.sync.aligned.m16n8k16.row.col.f32.f16.f16.f32 " \
        "{%0,%1,%2,%3}, {%4,%5,%6,%7}, {%8,%9}, {%0,%1,%2,%3};" \
        : "+f"((c)[0]), "+f"((c)[1]), "+f"((c)[2]), "+f"((c)[3]) \
        : "r"((a)[0]), "r"((a)[1]), "r"((a)[2]), "r"((a)[3]), \
          "r"((b)[0]), "r"((b)[1]))

#define LDSM4(r, addr) \
    asm volatile("ldmatrix.sync.aligned.m8n8.x4.shared.b16 {%0,%1,%2,%3}, [%4];" \
        : "=r"((r)[0]), "=r"((r)[1]), "=r"((r)[2]), "=r"((r)[3]) : "r"(addr))

#define LDSM4T(r, addr) \
    asm volatile("ldmatrix.sync.aligned.m8n8.x4.trans.shared.b16 {%0,%1,%2,%3}, [%4];" \
        : "=r"((r)[0]), "=r"((r)[1]), "=r"((r)[2]), "=r"((r)[3]) : "r"(addr))

__device__ __forceinline__ void cpa16s(uint32_t d, const void* gsrc)
{
    asm volatile("cp.async.cg.shared.global [%0], [%1], 16;" :: "r"(d), "l"(gsrc));
}
__device__ __forceinline__ void cpa_commit() { asm volatile("cp.async.commit_group;"); }
__device__ __forceinline__ void cpa_wait0()  { asm volatile("cp.async.wait_group 0;"); }
__device__ __forceinline__ void cpa_wait2()  { asm volatile("cp.async.wait_group 2;"); }

// ============================================================================
// 128x128 fp16 NN core: BK=32, 8 warps (4 in M x 2 in N), warp tile 32x64,
// 6-stage cp.async, 1 barrier per k-pair.
// smem/stage: A 128x(32h,80B stride)=10240, B 32x(128h,272B stride)=8704.
// ============================================================================
#define BIG_A 0
#define BIG_B 10240
#define BIG_BUF 18944
#define BIG_STAGES 6
#define BIG_SMEM (BIG_STAGES*BIG_BUF)

__device__ __forceinline__ void big_core(
    const __half* __restrict__ A, const __half* __restrict__ B,
    int N, int K, int m0, int n0, float c[2][8][4], char* smdyn)
{
    const int tid = threadIdx.x, lane = tid & 31, wid = tid >> 5;
    const int wm = (wid & 3) * 32, wn = (wid >> 2) * 64;
    const uint32_t sbase = (uint32_t)__cvta_generic_to_shared(smdyn);
    const int S = K / 32;

    auto issue = [&](int kt) {
        const uint32_t base = sbase + (kt % BIG_STAGES) * BIG_BUF;
        const int k0 = kt * 32;
        #pragma unroll
        for (int j = 0; j < 2; j++) {
            int ch = tid + j * 256, row = ch >> 2, cc = ch & 3;
            cpa16s(base + BIG_A + row * 80 + cc * 16, A + (size_t)(m0 + row) * K + k0 + cc * 8);
        }
        #pragma unroll
        for (int j = 0; j < 2; j++) {
            int ch = tid + j * 256, row = ch >> 4, cc = ch & 15;
            cpa16s(base + BIG_B + row * 272 + cc * 16, B + (size_t)(k0 + row) * N + n0 + cc * 8);
        }
        cpa_commit();
    };

    auto compute = [&](int s) {
        const uint32_t base = sbase + (s % BIG_STAGES) * BIG_BUF;
        #pragma unroll
        for (int ks = 0; ks < 2; ks++) {
            uint32_t a[2][4];
            #pragma unroll
            for (int mt = 0; mt < 2; mt++) {
                uint32_t addr = base + BIG_A
                    + (uint32_t)(wm + mt * 16 + (lane & 15)) * 80
                    + (uint32_t)(ks * 32 + (lane >> 4) * 16);
                LDSM4(a[mt], addr);
            }
            uint32_t b[4][4];
            #pragma unroll
            for (int bt = 0; bt < 4; bt++) {
                uint32_t addr = base + BIG_B
                    + (uint32_t)(ks * 16 + (lane & 15)) * 272
                    + (uint32_t)((wn + bt * 16) * 2 + (lane >> 4) * 16);
                LDSM4T(b[bt], addr);
            }
            #pragma unroll
            for (int mt = 0; mt < 2; mt++)
                #pragma unroll
                for (int nt = 0; nt < 8; nt++)
                    MMA_FP16(c[mt][nt], a[mt], (&b[nt >> 1][(nt & 1) * 2]));
        }
    };

    issue(0); issue(1); issue(2); issue(3);
    for (int s = 0; s < S; s += 2) {
        if (s + 2 < S) cpa_wait2(); else cpa_wait0();
        __syncthreads();
        if (s + 4 < S) issue(s + 4);
        if (s + 5 < S) issue(s + 5);
        compute(s);
        compute(s + 1);
    }
}

// ---- fp16 out, alpha scale (big batched GEMMs) ------------------------------
__global__ __launch_bounds__(256, 2)
void gemm_big_f16(const __half* __restrict__ A, const __half* __restrict__ B,
                  __half* __restrict__ C, int N, int K,
                  long long sA, long long sB, long long sC, float alpha)
{
    extern __shared__ char smdyn[];
    const int bz = blockIdx.z;
    A += (size_t)bz * sA; B += (size_t)bz * sB; C += (size_t)bz * sC;
    const int m0 = blockIdx.y * 128, n0 = blockIdx.x * 128;
    const int lane = threadIdx.x & 31, wid = threadIdx.x >> 5;
    const int wm = (wid & 3) * 32, wn = (wid >> 2) * 64;
    const int g = lane >> 2, t = lane & 3;
    float c[2][8][4] = {};
    big_core(A, B, N, K, m0, n0, c, smdyn);
    #pragma unroll
    for (int mt = 0; mt < 2; mt++)
        #pragma unroll
        for (int nt = 0; nt < 8; nt++) {
            int row = m0 + wm + mt * 16 + g;
            int col = n0 + wn + nt * 8 + 2 * t;
            *(__half2*)&C[(size_t)row * N + col] =
                __floats2half2_rn(alpha * c[mt][nt][0], alpha * c[mt][nt][1]);
            *(__half2*)&C[(size_t)(row + 8) * N + col] =
                __floats2half2_rn(alpha * c[mt][nt][2], alpha * c[mt][nt][3]);
        }
}

// ---- h: fp16 C = (A@B + bias + add)*scale (128x128) -------------------------
__global__ __launch_bounds__(256, 2)
void gemm_big_epH(const __half* __restrict__ A, const __half* __restrict__ B,
                  const float* __restrict__ bias, const float* __restrict__ add,
                  __half* __restrict__ C, int N, int K, float scale)
{
    extern __shared__ char smdyn[];
    const int m0 = blockIdx.y * 128, n0 = blockIdx.x * 128;
    const int lane = threadIdx.x & 31, wid = threadIdx.x >> 5;
    const int wm = (wid & 3) * 32, wn = (wid >> 2) * 64;
    const int g = lane >> 2, t = lane & 3;
    float c[2][8][4] = {};
    big_core(A, B, N, K, m0, n0, c, smdyn);
    #pragma unroll
    for (int mt = 0; mt < 2; mt++)
        #pragma unroll
        for (int nt = 0; nt < 8; nt++) {
            int row = m0 + wm + mt * 16 + g;
            int col = n0 + wn + nt * 8 + 2 * t;
            float2 bv = *(const float2*)&bias[col];
            size_t i0 = (size_t)row * N + col;
            size_t i1 = (size_t)(row + 8) * N + col;
            float2 d0 = *(const float2*)&add[i0];
            float2 d1 = *(const float2*)&add[i1];
            *(__half2*)&C[i0] = __floats2half2_rn((c[mt][nt][0] + bv.x + d0.x) * scale,
                                                  (c[mt][nt][1] + bv.y + d0.y) * scale);
            *(__half2*)&C[i1] = __floats2half2_rn((c[mt][nt][2] + bv.x + d1.x) * scale,
                                                  (c[mt][nt][3] + bv.y + d1.y) * scale);
        }
}

// ---- final out: fp32 C = (A@B + bias + add)*scale (128x128) -----------------
__global__ __launch_bounds__(256, 2)
void gemm_big_epF(const __half* __restrict__ A, const __half* __restrict__ B,
                  const float* __restrict__ bias, const float* __restrict__ add,
                  float* __restrict__ C, int N, int K, float scale)
{
    extern __shared__ char smdyn[];
    const int m0 = blockIdx.y * 128, n0 = blockIdx.x * 128;
    const int lane = threadIdx.x & 31, wid = threadIdx.x >> 5;
    const int wm = (wid & 3) * 32, wn = (wid >> 2) * 64;
    const int g = lane >> 2, t = lane & 3;
    float c[2][8][4] = {};
    big_core(A, B, N, K, m0, n0, c, smdyn);
    #pragma unroll
    for (int mt = 0; mt < 2; mt++)
        #pragma unroll
        for (int nt = 0; nt < 8; nt++) {
            int row = m0 + wm + mt * 16 + g;
            int col = n0 + wn + nt * 8 + 2 * t;
            float2 bv = *(const float2*)&bias[col];
            size_t i0 = (size_t)row * N + col;
            size_t i1 = (size_t)(row + 8) * N + col;
            float2 d0 = *(const float2*)&add[i0];
            float2 d1 = *(const float2*)&add[i1];
            *(float2*)&C[i0] = make_float2((c[mt][nt][0] + bv.x + d0.x) * scale,
                                           (c[mt][nt][1] + bv.y + d0.y) * scale);
            *(float2*)&C[i1] = make_float2((c[mt][nt][2] + bv.x + d1.x) * scale,
                                           (c[mt][nt][3] + bv.y + d1.y) * scale);
        }
}

// ============================================================================
// converts
// ============================================================================
__global__ void convert_f16(const float4* __restrict__ src, __half2* __restrict__ h2)
{
    const int i = blockIdx.x * 256 + threadIdx.x;
    float4 v = src[i];
    h2[2*i]     = __floats2half2_rn(v.x, v.y);
    h2[2*i + 1] = __floats2half2_rn(v.z, v.w);
}

// transpose + convert: dst[c][r] = fp16(src[r][c]);  src [R,Cd]
__global__ void transpose_cvt(const float* __restrict__ src, __half* __restrict__ dst,
                              int R, int Cd)
{
    __shared__ float t[32][33];
    const int c0 = blockIdx.x * 32, r0 = blockIdx.y * 32;
    const int tx = threadIdx.x, ty = threadIdx.y;   // 32 x 8
    #pragma unroll
    for (int j = 0; j < 4; j++)
        t[ty + 8*j][tx] = src[(size_t)(r0 + ty + 8*j) * Cd + c0 + tx];
    __syncthreads();
    #pragma unroll
    for (int j = 0; j < 4; j++)
        dst[(size_t)(c0 + ty + 8*j) * R + r0 + tx] = __float2half_rn(t[tx][ty + 8*j]);
}

// ============================================================================
// fused softmax: fp16 scores in g_af -> fp32 attn + fp16 in-place + partials.
// Warp-shuffle reductions: 2 barriers per row instead of 16.
// ============================================================================
__global__ void softmax_fused(__half* __restrict__ af, float* __restrict__ attn,
                              float* __restrict__ part)
{
    const int b = blockIdx.y, rg = blockIdx.x;
    const int tid = threadIdx.x, lane = tid & 31, wid = tid >> 5;
    __shared__ float redmax[8], redsum[8];
    float acc[8] = {};

    for (int r = 0; r < RPB; r++) {
        const size_t row = (size_t)b * Tc + rg * RPB + r;
        __half* ps = af + row * Sc;
        float* pa = attn + row * Sc;
        float v[8];
        float mx = -CUDART_INF_F;
        #pragma unroll
        for (int i = 0; i < 8; i++) { v[i] = __half2float(ps[tid + i*256]); mx = fmaxf(mx, v[i]); }
        #pragma unroll
        for (int o = 16; o; o >>= 1) mx = fmaxf(mx, __shfl_xor_sync(0xffffffffu, mx, o));
        if (lane == 0) redmax[wid] = mx;
        __syncthreads();
        #pragma unroll
        for (int w = 0; w < 8; w++) mx = fmaxf(mx, redmax[w]);
        float sum = 0.0f;
        #pragma unroll
        for (int i = 0; i < 8; i++) { v[i] = __expf(v[i] - mx); sum += v[i]; }
        #pragma unroll
        for (int o = 16; o; o >>= 1) sum += __shfl_xor_sync(0xffffffffu, sum, o);
        if (lane == 0) redsum[wid] = sum;
        __syncthreads();
        sum = 0.0f;
        #pragma unroll
        for (int w = 0; w < 8; w++) sum += redsum[w];
        const float inv = 1.0f / sum;
        #pragma unroll
        for (int i = 0; i < 8; i++) {
            float a = v[i] * inv;
            pa[tid + i*256] = a;
            ps[tid + i*256] = __float2half_rn(a);
            acc[i] += a;
        }
    }
    float* pp = part + ((size_t)b * NGRP + rg) * Sc;
    #pragma unroll
    for (int i = 0; i < 8; i++) pp[tid + i*256] = acc[i];
}

__global__ void xmean_reduce(const float* __restrict__ part)
{
    const int b = blockIdx.y;
    const int s = blockIdx.x * 256 + threadIdx.x;
    const float* pp = part + (size_t)b * NGRP * Sc + s;
    float sum = 0.0f;
    #pragma unroll 8
    for (int g = 0; g < NGRP; g++) sum += pp[(size_t)g * Sc];
    g_xmean[b * Sc + s] = sum * (1.0f / Tc);
}

// ---------------- row inv-norms of strided enc_values + aa -----------------
__global__ void norm_aa_k(const float* __restrict__ V)
{
    const int b = blockIdx.x;
    const int w = threadIdx.x >> 5, lane = threadIdx.x & 31;
    for (int n = w; n < NSEL; n += 8) {
        const float* row = V + ((size_t)b * Sc + (size_t)n * STRIDEc) * Ec;
        float s = 0.0f;
        for (int e = lane; e < Ec; e += 32) { float x = row[e]; s = fmaf(x, x, s); }
        #pragma unroll
        for (int o = 16; o; o >>= 1) s += __shfl_down_sync(0xffffffffu, s, o);
        if (lane == 0) {
            g_invn[b * NSEL + n] = rsqrtf(s);
            g_aa[b * NSEL + n]   = g_xmean[b * Sc + n * STRIDEc];
        }
    }
}

// ---------------- L[b][n][m] = aa_n aa_m * <v_n,v_m>/(|v_n||v_m|) ----------
__global__ void L_k(const float* __restrict__ V)
{
    const int b = blockIdx.x, n = blockIdx.y;
    __shared__ float vn[Ec];
    const float* rn = V + ((size_t)b * Sc + (size_t)n * STRIDEc) * Ec;
    for (int e = threadIdx.x; e < Ec; e += 128) vn[e] = rn[e];
    __syncthreads();
    const int m = threadIdx.x;
    if (m < NSEL) {
        const float* rm = V + ((size_t)b * Sc + (size_t)m * STRIDEc) * Ec;
        float d = 0.0f;
        for (int e = 0; e < Ec; e++) d = fmaf(vn[e], rm[e], d);
        float val = d * g_invn[b*NSEL + n] * g_invn[b*NSEL + m]
                      * g_aa[b*NSEL + n]   * g_aa[b*NSEL + m];
        g_L[((size_t)b * NSEL + n) * NSEL + m] = val;
    }
}

// numpy-style argmax of logf(D[n]*mask[n]): first NaN wins; strict > keeps first max
__device__ __forceinline__ int argmax_logDm(const float* D, const float* msk)
{
    int J = 0; float best = -CUDART_INF_F; bool done = false;
    for (int n = 0; n < NSEL && !done; n++) {
        float v = logf(D[n] * msk[n]);
        if (isnan(v)) { J = n; done = true; }
        else if (v > best) { best = v; J = n; }
    }
    return J;
}

// ---------------- greedy bfgm selection (sequential, tiny) -----------------
__global__ void bfgm_k()
{
    const int b = blockIdx.x, tid = threadIdx.x;  // 128 threads
    __shared__ float Cm[NSEL][MS];
    __shared__ float D[NSEL], msk[NSEL], cjs[MS];
    __shared__ float djs;
    __shared__ int Jsh, sel[MS];
    const float* L = g_L + (size_t)b * NSEL * NSEL;

    if (tid < NSEL) {
        D[tid] = L[(size_t)tid * NSEL + tid];
        msk[tid] = 1.0f;
        #pragma unroll
        for (int k = 0; k < MS; k++) Cm[tid][k] = 0.0f;
    }
    __syncthreads();
    if (tid == 0) {
        int J = argmax_logDm(D, msk);
        Jsh = J; msk[J] = 0.0f; sel[0] = J;
    }
    __syncthreads();

    for (int t = 1; t < MS; t++) {
        const int J = Jsh;
        if (tid < MS) cjs[tid] = Cm[J][tid];
        if (tid == 0) djs = D[J];
        __syncthreads();
        if (tid < NSEL) {
            float Lj = L[(size_t)J * NSEL + tid];
            float cd = 0.0f;
            #pragma unroll
            for (int k = 0; k < MS; k++) cd = fmaf(Cm[tid][k], cjs[k], cd);
            float e = (Lj - cd) / djs * msk[tid];
            Cm[tid][t] = e;
            D[tid] -= e * e;
        }
        __syncthreads();
        if (tid == 0) {
            int Jn = argmax_logDm(D, msk);
            Jsh = Jn; msk[Jn] = 0.0f; sel[t] = Jn;
        }
        __syncthreads();
    }
    if (tid == 0) {
        for (int i = 1; i < MS; i++) {          // insertion sort ascending
            int key = sel[i], j = i - 1;
            while (j >= 0 && sel[j] > key) { sel[j+1] = sel[j]; j--; }
            sel[j+1] = key;
        }
        for (int k = 0; k < MS; k++) g_mu[b*MS + k] = sel[k];
    }
}

// ---------------- gaussian mixture -> softmax(dist) -> KL partial ----------
__global__ void distkl_k()
{
    const int b = blockIdx.x, tid = threadIdx.x;   // 256 threads, 8 s-values each
    __shared__ float red[256];
    int mus[MS];
    #pragma unroll
    for (int k = 0; k < MS; k++) mus[k] = g_mu[b*MS + k];

    float g[8];
    float mx = -CUDART_INF_F;
    #pragma unroll
    for (int i = 0; i < 8; i++) {
        const int s = tid + i*256;
        float acc = 0.0f;
        #pragma unroll
        for (int k = 0; k < MS; k++) {
            float z = (float)s - (float)mus[k];
            acc += expf(-z*z * (1.0f/18.0f));        // 2*sigma^2 = 18
        }
        acc *= 0.13298076013381091f;                 // 1/(sqrt(2pi)*3)
        g[i] = acc; mx = fmaxf(mx, acc);
    }
    red[tid] = mx; __syncthreads();
    for (int s = 128; s > 0; s >>= 1) { if (tid < s) red[tid] = fmaxf(red[tid], red[tid+s]); __syncthreads(); }
    mx = red[0]; __syncthreads();
    float sum = 0.0f;
    #pragma unroll
    for (int i = 0; i < 8; i++) { g[i] = expf(g[i] - mx); sum += g[i]; }
    red[tid] = sum; __syncthreads();
    for (int s = 128; s > 0; s >>= 1) { if (tid < s) red[tid] += red[tid+s]; __syncthreads(); }
    const float inv = 1.0f / red[0];
    __syncthreads();

    float kl = 0.0f;
    #pragma unroll
    for (int i = 0; i < 8; i++) {
        const int s = tid + i*256;
        float xm = g_xmean[b*Sc + s];
        kl += xm * (logf(xm) - g[i] * inv);
    }
    red[tid] = kl; __syncthreads();
    for (int s = 128; s > 0; s >>= 1) { if (tid < s) red[tid] += red[tid+s]; __syncthreads(); }
    if (tid == 0) atomicAdd(&g_kl, red[0]);
}

// ---------------- launch ----------------------------------------------------
extern "C" void kernel_launch(void* const* d_in, const int* in_sizes, int n_in,
                              void* d_out, int out_size)
{
    const float* x  = (const float*)d_in[0];
    const float* te = (const float*)d_in[1];
    const float* ek = (const float*)d_in[2];   // [B,E,S]
    const float* ev = (const float*)d_in[3];   // [B,S,E]
    const float* Wi = (const float*)d_in[4];   // [E,C]
    const float* bi = (const float*)d_in[5];
    const float* Wo = (const float*)d_in[6];   // [C,E]
    const float* bo = (const float*)d_in[7];

    float* out  = (float*)d_out;                              // [B,T,C]
    float* attn = out + (size_t)Bc * Tc * Cc;                 // [B,T,S]
    float* klp  = attn + (size_t)Bc * Tc * Sc;                // scalar

    __half *xf, *hf, *ekf, *evf, *af, *o1f, *WiT, *WoT;
    float* part;
    cudaGetSymbolAddress((void**)&xf,  g_xf);
    cudaGetSymbolAddress((void**)&hf,  g_hf);
    cudaGetSymbolAddress((void**)&ekf, g_ekf);
    cudaGetSymbolAddress((void**)&evf, g_evf);
    cudaGetSymbolAddress((void**)&af,  g_af);
    cudaGetSymbolAddress((void**)&o1f, g_o1f);
    cudaGetSymbolAddress((void**)&WiT, g_WiT);
    cudaGetSymbolAddress((void**)&WoT, g_WoT);
    cudaGetSymbolAddress((void**)&part, g_part);

    cudaFuncSetAttribute(gemm_big_f16, cudaFuncAttributeMaxDynamicSharedMemorySize, BIG_SMEM);
    cudaFuncSetAttribute(gemm_big_epH, cudaFuncAttributeMaxDynamicSharedMemorySize, BIG_SMEM);
    cudaFuncSetAttribute(gemm_big_epF, cudaFuncAttributeMaxDynamicSharedMemorySize, BIG_SMEM);

    const float SQ05 = 0.70710678118654752f;
    const float SQS  = 45.25483399593904f;    // s*sqrt(1/s), s=2048

    // converts / weight transposes
    const int nEK4 = Bc * Ec * Sc / 4;
    const int nX4  = Bc * Tc * Cc / 4;
    convert_f16<<<nEK4 / 256, 256>>>((const float4*)ek, (__half2*)ekf);
    convert_f16<<<nEK4 / 256, 256>>>((const float4*)ev, (__half2*)evf);
    convert_f16<<<nX4 / 256, 256>>>((const float4*)x, (__half2*)xf);
    transpose_cvt<<<dim3(Cc/32, Ec/32), dim3(32, 8)>>>(Wi, WiT, Ec, Cc);  // WiT [C,E]
    transpose_cvt<<<dim3(Ec/32, Cc/32), dim3(32, 8)>>>(Wo, WoT, Cc, Ec);  // WoT [E,C]

    // h = (x @ Wi^T + bi + te)*sqrt(.5)  -> fp16 (128x128 tile)
    gemm_big_epH<<<dim3(Ec/128, (Bc*Tc)/128, 1), 256, BIG_SMEM>>>(
        xf, WiT, bi, te, hf, Ec, Cc, SQ05);

    // scores = h @ enc_keys -> fp16 into g_af (128x128 tile)
    gemm_big_f16<<<dim3(Sc/128, Tc/128, Bc), 256, BIG_SMEM>>>(
        hf, ekf, af, Sc, Ec,
        (long long)Tc*Ec, (long long)Ec*Sc, (long long)Tc*Sc, 1.0f);

    // softmax (fp16 in, fp32 attn out + fp16 in-place) + xmean partials
    softmax_fused<<<dim3(NGRP, Bc), 256>>>(af, attn, part);
    xmean_reduce<<<dim3(Sc/256, Bc), 256>>>(part);

    // out1 = attn @ enc_values * sqrt(S)  -> fp16 (128x128 tile)
    gemm_big_f16<<<dim3(Ec/128, Tc/128, Bc), 256, BIG_SMEM>>>(
        af, evf, o1f, Ec, Sc,
        (long long)Tc*Sc, (long long)Sc*Ec, (long long)Tc*Ec, SQS);

    // out = (out1 @ Wo^T + bo + x)*sqrt(.5)  (128x128 tile)
    gemm_big_epF<<<dim3(Cc/128, (Bc*Tc)/128, 1), 256, BIG_SMEM>>>(
        o1f, WoT, bo, x, out, Cc, Ec, SQ05);

    // DPP side path
    init_k<<<1, 1>>>();
    norm_aa_k<<<Bc, 256>>>(ev);
    L_k<<<dim3(Bc, NSEL), 128>>>(ev);
    bfgm_k<<<Bc, 128>>>();
    distkl_k<<<Bc, 256>>>();
    final_k<<<1, 1>>>(klp);
}